// round 8
// baseline (speedup 1.0000x reference)
#include <cuda_runtime.h>
#include <cstdint>

// Problem constants
#define N_TOK 16384
#define DIM   1024
#define HID   4096
#define HHALF 2048
#define NEXP  8
#define EPSLN 1e-5f
#define EPSG  1e-3f      // router top2/top3 gap threshold for exact repair

// CTA tile
#define BM 128
#define BN 256
#define BSTRD 264     // BN + 8 pad, conflict-free B frag reads

// ---------------- scratch (static device globals) -----------------------------
__device__ float g_xn [(size_t)N_TOK * DIM];
__device__ float g_xnl[(size_t)N_TOK * DIM];
__device__ float g_hr [(size_t)N_TOK * HHALF];
__device__ float g_h  [(size_t)(2 * N_TOK) * HID];
__device__ float g_y  [(size_t)(2 * N_TOK) * DIM];
__device__ int   g_cnt[NEXP];
__device__ int   g_off[NEXP];
__device__ int   g_fill[NEXP];
__device__ int   g_e12[N_TOK];
__device__ float g_g1[N_TOK];
__device__ float g_g2[N_TOK];
__device__ int   g_list[2 * N_TOK];
__device__ int   g_s1[N_TOK];
__device__ int   g_s2[N_TOK];
__device__ int   g_nflag;
__device__ int   g_flaglist[N_TOK];

// ---------------- helpers ------------------------------------------------------
__device__ __forceinline__ uint32_t smem_u32(const void* p) {
    uint32_t a;
    asm("{ .reg .u64 t; cvta.to.shared.u64 t, %1; cvt.u32.u64 %0, t; }" : "=r"(a) : "l"(p));
    return a;
}
__device__ __forceinline__ float rtf32(float x) {
    float r; asm("cvt.rna.tf32.f32 %0, %1;" : "=f"(r) : "f"(x)); return r;
}
#define CP16(dst, src) \
    asm volatile("cp.async.cg.shared.global [%0], [%1], 16;" :: "r"(dst), "l"(src) : "memory")
#define CP_COMMIT() asm volatile("cp.async.commit_group;" ::: "memory")
#define CP_WAIT1()  asm volatile("cp.async.wait_group 1;" ::: "memory")
#define CP_WAIT0()  asm volatile("cp.async.wait_group 0;" ::: "memory")

__device__ __forceinline__ void mma8(float c[4], const uint32_t a[4], const uint32_t b[2]) {
    asm volatile(
        "mma.sync.aligned.m16n8k8.row.col.f32.tf32.tf32.f32 "
        "{%0,%1,%2,%3}, {%4,%5,%6,%7}, {%8,%9}, {%0,%1,%2,%3};"
        : "+f"(c[0]), "+f"(c[1]), "+f"(c[2]), "+f"(c[3])
        : "r"(a[0]), "r"(a[1]), "r"(a[2]), "r"(a[3]), "r"(b[0]), "r"(b[1]));
}

// ---------------- LayerNorm: writes tf32 hi + lo residual ----------------------
__global__ void ln_kernel(const float* __restrict__ x,
                          const float* __restrict__ gam,
                          const float* __restrict__ bet) {
    int row = blockIdx.x;
    const float* xr = x + (size_t)row * DIM;
    float s = 0.f, ss = 0.f;
    for (int i = threadIdx.x; i < DIM; i += 256) {
        float v = xr[i];
        s += v; ss += v * v;
    }
    __shared__ float sh[64];
    for (int o = 16; o; o >>= 1) {
        s  += __shfl_xor_sync(0xFFFFFFFFu, s,  o);
        ss += __shfl_xor_sync(0xFFFFFFFFu, ss, o);
    }
    int w = threadIdx.x >> 5, l = threadIdx.x & 31;
    if (l == 0) { sh[w] = s; sh[w + 32] = ss; }
    __syncthreads();
    if (w == 0) {
        s  = (l < 8) ? sh[l] : 0.f;
        ss = (l < 8) ? sh[l + 32] : 0.f;
        for (int o = 4; o; o >>= 1) {
            s  += __shfl_xor_sync(0xFFFFFFFFu, s,  o);
            ss += __shfl_xor_sync(0xFFFFFFFFu, ss, o);
        }
        if (l == 0) { sh[0] = s; sh[1] = ss; }
    }
    __syncthreads();
    float mu  = sh[0] * (1.0f / DIM);
    float var = sh[1] * (1.0f / DIM) - mu * mu;
    float r   = rsqrtf(var + EPSLN);
    for (int i = threadIdx.x; i < DIM; i += 256) {
        float v = (xr[i] - mu) * r * gam[i] + bet[i];
        float h = rtf32(v);
        g_xn [(size_t)row * DIM + i] = h;
        g_xnl[(size_t)row * DIM + i] = v - h;
    }
}

// ---------------- Router logits + softmax top-2 + gates + gap flag -------------
__global__ void router_kernel(const float* __restrict__ w2,
                              const float* __restrict__ b2) {
    int warp = threadIdx.x >> 5, lane = threadIdx.x & 31;
    int t = blockIdx.x * 8 + warp;
    const float* hrow = g_hr + (size_t)t * HHALF;
    float acc[NEXP] = {};
    for (int i = lane; i < HHALF; i += 32) {
        float v = hrow[i];
        const float4* wp = (const float4*)(w2 + i * NEXP);
        float4 w0 = __ldg(wp), w1 = __ldg(wp + 1);
        acc[0] += v * w0.x; acc[1] += v * w0.y; acc[2] += v * w0.z; acc[3] += v * w0.w;
        acc[4] += v * w1.x; acc[5] += v * w1.y; acc[6] += v * w1.z; acc[7] += v * w1.w;
    }
    for (int o = 16; o; o >>= 1)
#pragma unroll
        for (int e = 0; e < NEXP; e++)
            acc[e] += __shfl_xor_sync(0xFFFFFFFFu, acc[e], o);
    if (lane == 0) {
        float l[NEXP];
#pragma unroll
        for (int e = 0; e < NEXP; e++) l[e] = acc[e] + b2[e];
        int e1 = 0;
        for (int e = 1; e < NEXP; e++) if (l[e] > l[e1]) e1 = e;
        int e2 = -1;
        for (int e = 0; e < NEXP; e++) {
            if (e == e1) continue;
            if (e2 < 0 || l[e] > l[e2]) e2 = e;
        }
        int e3 = -1;
        for (int e = 0; e < NEXP; e++) {
            if (e == e1 || e == e2) continue;
            if (e3 < 0 || l[e] > l[e3]) e3 = e;
        }
        float ed  = expf(l[e2] - l[e1]);
        float inv = 1.f / (1.f + ed);
        g_e12[t] = e1 | (e2 << 8);
        g_g1[t] = inv;
        g_g2[t] = ed * inv;
        if (l[e2] - l[e3] < EPSG) {
            int pos = atomicAdd(&g_nflag, 1);
            g_flaglist[pos] = t;
        }
    }
}

// ---------------- exact fp32 repair of flagged tokens (4 tokens per CTA) -------
__global__ void __launch_bounds__(256) repair_kernel(
        const float* __restrict__ w1, const float* __restrict__ b1,
        const float* __restrict__ w2, const float* __restrict__ b2) {
    int nf = g_nflag;
    int base = blockIdx.x * 4;
    if (base >= nf) return;
    int nv = nf - base; if (nv > 4) nv = 4;

    __shared__ float xs[4][DIM];
    __shared__ float slog[4][NEXP];
    int tid = threadIdx.x;
    int toks[4];
#pragma unroll
    for (int j = 0; j < 4; j++)
        toks[j] = g_flaglist[(j < nv) ? base + j : base];

    for (int j = 0; j < 4; j++) {
        const float* xh = g_xn  + (size_t)toks[j] * DIM;
        const float* xl = g_xnl + (size_t)toks[j] * DIM;
        for (int i = tid; i < DIM; i += 256) xs[j][i] = xh[i] + xl[i];
    }
    if (tid < 4 * NEXP) ((float*)slog)[tid] = b2[tid & (NEXP - 1)];
    __syncthreads();

    float pl[4][NEXP] = {};
    for (int c0 = 0; c0 < HHALF / 256; c0++) {
        int c = tid + c0 * 256;
        float a0 = b1[c], a1 = a0, a2 = a0, a3 = a0;
        const float* wc = w1 + c;
        for (int k = 0; k < DIM; k++) {
            float wv = __ldg(wc + (size_t)k * HHALF);
            a0 += xs[0][k] * wv;
            a1 += xs[1][k] * wv;
            a2 += xs[2][k] * wv;
            a3 += xs[3][k] * wv;
        }
        a0 = fmaxf(a0, 0.f); a1 = fmaxf(a1, 0.f);
        a2 = fmaxf(a2, 0.f); a3 = fmaxf(a3, 0.f);
#pragma unroll
        for (int e = 0; e < NEXP; e++) {
            float we = __ldg(w2 + (size_t)c * NEXP + e);
            pl[0][e] += a0 * we;
            pl[1][e] += a1 * we;
            pl[2][e] += a2 * we;
            pl[3][e] += a3 * we;
        }
    }
#pragma unroll
    for (int j = 0; j < 4; j++)
#pragma unroll
        for (int e = 0; e < NEXP; e++)
            atomicAdd(&slog[j][e], pl[j][e]);
    __syncthreads();

    if (tid < 4 && tid < nv) {
        int j = tid, t = toks[j];
        float l[NEXP];
#pragma unroll
        for (int e = 0; e < NEXP; e++) l[e] = slog[j][e];
        int e1 = 0;
        for (int e = 1; e < NEXP; e++) if (l[e] > l[e1]) e1 = e;
        int e2 = -1;
        for (int e = 0; e < NEXP; e++) {
            if (e == e1) continue;
            if (e2 < 0 || l[e] > l[e2]) e2 = e;
        }
        float ed  = expf(l[e2] - l[e1]);
        float inv = 1.f / (1.f + ed);
        g_e12[t] = e1 | (e2 << 8);
        g_g1[t] = inv;
        g_g2[t] = ed * inv;
    }
}

__global__ void zero_cnt_kernel() {
    if (threadIdx.x < NEXP) g_cnt[threadIdx.x] = 0;
    if (threadIdx.x == 0) g_nflag = 0;
}
__global__ void count_kernel() {
    int t = blockIdx.x * 256 + threadIdx.x;
    int e12 = g_e12[t];
    atomicAdd(&g_cnt[e12 & 0xFF], 1);
    atomicAdd(&g_cnt[e12 >> 8], 1);
}
__global__ void scan_kernel() {
    if (threadIdx.x == 0) {
        int s = 0;
        for (int e = 0; e < NEXP; e++) { g_off[e] = s; s += g_cnt[e]; g_fill[e] = 0; }
    }
}
__global__ void place_kernel() {
    int t = blockIdx.x * 256 + threadIdx.x;
    int e12 = g_e12[t];
    int e1 = e12 & 0xFF, e2 = e12 >> 8;
    int s1 = g_off[e1] + atomicAdd(&g_fill[e1], 1);
    g_list[s1] = t; g_s1[t] = s1;
    int s2 = g_off[e2] + atomicAdd(&g_fill[e2], 1);
    g_list[s2] = t; g_s2[t] = s2;
}

// ---------------- final combine: out = x + g1*y[s1] + g2*y[s2] ------------------
__global__ void combine_kernel(const float* __restrict__ x, float* __restrict__ out) {
    int t = blockIdx.x;
    int s1 = g_s1[t], s2 = g_s2[t];
    float a = g_g1[t], b = g_g2[t];
    const float4* xr = (const float4*)(x   + (size_t)t  * DIM);
    const float4* y1 = (const float4*)(g_y + (size_t)s1 * DIM);
    const float4* y2 = (const float4*)(g_y + (size_t)s2 * DIM);
    float4* o = (float4*)(out + (size_t)t * DIM);
    int i = threadIdx.x;
    float4 xv = xr[i], v1 = y1[i], v2 = y2[i];
    float4 r;
    r.x = xv.x + a * v1.x + b * v2.x;
    r.y = xv.y + a * v1.y + b * v2.y;
    r.z = xv.z + a * v1.z + b * v2.z;
    r.w = xv.w + a * v1.w + b * v2.w;
    o[i] = r;
}

// ---------------- tf32 mma.sync GEMM (128x256 CTA, 64x64 warp tiles) ------------
// 3-stage cp.async pipeline, 1 CTA/SM. All modes single-pass tf32, BKC=32.
// MODE 0: g_hr = relu(xn @ r_w1 + b)                   M=16384 N=2048 K=1024
// MODE 1: g_h  = rtf32(relu(gather(xn) @ e_w1 + b))    M=cnt   N=4096 K=1024
// MODE 2: g_y  = g_h @ e_w2 + b   (compact rows)       M=cnt   N=1024 K=4096
template <int MODE>
__global__ void __launch_bounds__(256, 1)
moe_mma(const float* __restrict__ Wbase, const float* __restrict__ bias) {
    constexpr int Kd  = (MODE == 2) ? HID : DIM;
    constexpr int Nd  = (MODE == 0) ? HHALF : (MODE == 1) ? HID : DIM;
    constexpr int BKC = 32;
    constexpr int NC  = Kd / BKC;
    constexpr int AST = BKC + 4;
    constexpr int ASZ = BM * AST;
    constexpr int BSZ = BKC * BSTRD;
    constexpr int STG = ASZ + BSZ;
    constexpr int AJ  = BKC / 8;
    constexpr int BJ  = BKC / 4;

    int bm = blockIdx.y * BM, bn = blockIdx.x * BN;
    int e = 0, cnt = N_TOK, base = 0;
    if (MODE != 0) {
        e = blockIdx.z;
        cnt = g_cnt[e];
        if (bm >= cnt) return;
        base = g_off[e];
    }
    const float* Wh = (MODE == 0) ? Wbase
                    : (MODE == 1) ? Wbase + (size_t)e * DIM * HID
                                  : Wbase + (size_t)e * HID * DIM;
    const float* bp = bias + ((MODE == 0) ? 0 : (MODE == 1) ? e * HID : e * DIM);

    extern __shared__ float sm[];
    uint32_t smb = smem_u32(sm);

    int tid = threadIdx.x, lane = tid & 31, wid = tid >> 5;
    int wm = (wid >> 2) * 64, wn = (wid & 3) * 64;

    // ---- per-thread load slots ----
    const float* ah[AJ];
    const float* bh[BJ];
    uint32_t adst[AJ], bdst[BJ];
#pragma unroll
    for (int j = 0; j < AJ; j++) {
        int id = tid + 256 * j;
        int row = id / (BKC / 4), c4 = id % (BKC / 4);
        adst[j] = (uint32_t)row * (AST * 4) + c4 * 16;
        int r = bm + row;
        if (MODE == 1) {
            int rr = (r < cnt) ? r : cnt - 1;
            ah[j] = g_xn + (size_t)g_list[base + rr] * DIM + c4 * 4;
        } else if (MODE == 2) {
            int rr = (r < cnt) ? r : cnt - 1;
            ah[j] = g_h + (size_t)(base + rr) * HID + c4 * 4;
        } else {
            ah[j] = g_xn + (size_t)r * DIM + c4 * 4;
        }
    }
#pragma unroll
    for (int j = 0; j < BJ; j++) {
        int id = tid + 256 * j;
        int kr = id >> 6, c = id & 63;
        bdst[j] = (uint32_t)kr * (BSTRD * 4) + c * 16;
        bh[j] = Wh + (size_t)kr * Nd + bn + c * 4;
    }

    auto load = [&](int i, int st) {
        uint32_t s0 = smb + (uint32_t)st * STG * 4;
        uint32_t b0 = s0 + ASZ * 4;
        int ko = i * BKC;
        size_t bko = (size_t)ko * Nd;
#pragma unroll
        for (int j = 0; j < AJ; j++) CP16(s0 + adst[j], ah[j] + ko);
#pragma unroll
        for (int j = 0; j < BJ; j++) CP16(b0 + bdst[j], bh[j] + bko);
        CP_COMMIT();
    };

    float c[4][8][4] = {};
    load(0, 0);
    load(1, 1);

    int lr = lane >> 2, lc = lane & 3;
    for (int i = 0; i < NC; i++) {
        int st = i % 3;
        if (i + 2 < NC) { CP_WAIT1(); } else { CP_WAIT0(); }
        __syncthreads();
        if (i + 2 < NC) load(i + 2, (i + 2) % 3);

        const uint32_t* Au = (const uint32_t*)(sm + st * STG);
        const uint32_t* Bu = Au + ASZ;
#pragma unroll
        for (int ks = 0; ks < BKC / 8; ks++) {
            uint32_t a[4][4], b[8][2];
#pragma unroll
            for (int mt = 0; mt < 4; mt++) {
                const uint32_t* ap = Au + (wm + mt * 16 + lr) * AST + ks * 8 + lc;
                a[mt][0] = ap[0];
                a[mt][1] = ap[8 * AST];
                a[mt][2] = ap[4];
                a[mt][3] = ap[8 * AST + 4];
            }
#pragma unroll
            for (int nt = 0; nt < 8; nt++) {
                const uint32_t* bpp = Bu + (ks * 8 + lc) * BSTRD + wn + nt * 8 + lr;
                b[nt][0] = bpp[0];
                b[nt][1] = bpp[4 * BSTRD];
            }
#pragma unroll
            for (int mt = 0; mt < 4; mt++)
#pragma unroll
                for (int nt = 0; nt < 8; nt++)
                    mma8(c[mt][nt], a[mt], b[nt]);
        }
    }

    // ---------------- epilogue ----------------
#pragma unroll
    for (int mt = 0; mt < 4; mt++) {
#pragma unroll
        for (int half = 0; half < 2; half++) {
            int r = bm + wm + mt * 16 + lr + half * 8;
            if (MODE != 0 && r >= cnt) continue;
            float* row;
            if (MODE == 0)      row = g_hr + (size_t)r * HHALF;
            else if (MODE == 1) row = g_h  + (size_t)(base + r) * HID;
            else                row = g_y  + (size_t)(base + r) * DIM;
#pragma unroll
            for (int nt = 0; nt < 8; nt++) {
                int col = bn + wn + nt * 8 + lc * 2;
                float v0 = c[mt][nt][half * 2]     + bp[col];
                float v1 = c[mt][nt][half * 2 + 1] + bp[col + 1];
                float2 st2;
                if (MODE == 0) {
                    st2.x = fmaxf(v0, 0.f); st2.y = fmaxf(v1, 0.f);
                } else if (MODE == 1) {
                    st2.x = rtf32(fmaxf(v0, 0.f)); st2.y = rtf32(fmaxf(v1, 0.f));
                } else {
                    st2.x = v0; st2.y = v1;
                }
                *(float2*)(row + col) = st2;
            }
        }
    }
}

// ---------------- launch ---------------------------------------------------------
extern "C" void kernel_launch(void* const* d_in, const int* in_sizes, int n_in,
                              void* d_out, int out_size) {
    const float* x    = (const float*)d_in[0];
    const float* ln_g = (const float*)d_in[1];
    const float* ln_b = (const float*)d_in[2];
    const float* r_w1 = (const float*)d_in[3];
    const float* r_b1 = (const float*)d_in[4];
    const float* r_w2 = (const float*)d_in[5];
    const float* r_b2 = (const float*)d_in[6];
    const float* e_w1 = (const float*)d_in[7];
    const float* e_b1 = (const float*)d_in[8];
    const float* e_w2 = (const float*)d_in[9];
    const float* e_b2 = (const float*)d_in[10];
    float* out = (float*)d_out;

    const int SMEM_P = 3 * (BM * 36 + 32 * BSTRD) * 4;   // 156672

    static int configured = 0;
    if (!configured) {
        cudaFuncSetAttribute(moe_mma<0>, cudaFuncAttributeMaxDynamicSharedMemorySize, SMEM_P);
        cudaFuncSetAttribute(moe_mma<1>, cudaFuncAttributeMaxDynamicSharedMemorySize, SMEM_P);
        cudaFuncSetAttribute(moe_mma<2>, cudaFuncAttributeMaxDynamicSharedMemorySize, SMEM_P);
        configured = 1;
    }

    zero_cnt_kernel<<<1, 32>>>();
    ln_kernel<<<N_TOK, 256>>>(x, ln_g, ln_b);

    // router path: 1-pass tf32 GEMM -> logits + gap flags -> exact repair -> dispatch
    moe_mma<0><<<dim3(HHALF / BN, N_TOK / BM), 256, SMEM_P>>>(r_w1, r_b1);
    router_kernel<<<N_TOK / 8, 256>>>(r_w2, r_b2);
    repair_kernel<<<N_TOK / 4, 256>>>(r_w1, r_b1, r_w2, r_b2);
    count_kernel<<<N_TOK / 256, 256>>>();
    scan_kernel<<<1, 32>>>();
    place_kernel<<<N_TOK / 256, 256>>>();

    // expert path (raw fp32 weights; HW truncates to tf32)
    moe_mma<1><<<dim3(HID / BN, N_TOK / BM, NEXP), 256, SMEM_P>>>(e_w1, e_b1);
    moe_mma<2><<<dim3(DIM / BN, N_TOK / BM, NEXP), 256, SMEM_P>>>(e_w2, e_b2);

    // out = x + g1*y1 + g2*y2
    combine_kernel<<<N_TOK, 256>>>(x, out);
}

// round 9
// speedup vs baseline: 1.0319x; 1.0319x over previous
#include <cuda_runtime.h>
#include <cstdint>

// Problem constants
#define N_TOK 16384
#define DIM   1024
#define HID   4096
#define HHALF 2048
#define NEXP  8
#define EPSLN 1e-5f
#define EPSG  1e-3f      // router top2/top3 gap threshold for exact repair

// CTA tile
#define BM 128
#define BN 256
#define BSTRD 264     // BN + 8 pad, conflict-free B frag reads

// ---------------- scratch (static device globals) -----------------------------
__device__ float g_xn [(size_t)N_TOK * DIM];
__device__ float g_xnl[(size_t)N_TOK * DIM];
__device__ float g_hr [(size_t)N_TOK * HHALF];
__device__ float g_h  [(size_t)(2 * N_TOK) * HID];
__device__ float g_y  [(size_t)(2 * N_TOK) * DIM];
__device__ int   g_cnt[NEXP];
__device__ int   g_off[NEXP];
__device__ int   g_fill[NEXP];
__device__ int   g_e12[N_TOK];
__device__ float g_g1[N_TOK];
__device__ float g_g2[N_TOK];
__device__ int   g_list[2 * N_TOK];
__device__ int   g_s1[N_TOK];
__device__ int   g_s2[N_TOK];
__device__ int   g_nflag;
__device__ int   g_flaglist[N_TOK];

// ---------------- helpers ------------------------------------------------------
__device__ __forceinline__ uint32_t smem_u32(const void* p) {
    uint32_t a;
    asm("{ .reg .u64 t; cvta.to.shared.u64 t, %1; cvt.u32.u64 %0, t; }" : "=r"(a) : "l"(p));
    return a;
}
__device__ __forceinline__ float rtf32(float x) {
    float r; asm("cvt.rna.tf32.f32 %0, %1;" : "=f"(r) : "f"(x)); return r;
}
#define CP16(dst, src) \
    asm volatile("cp.async.cg.shared.global [%0], [%1], 16;" :: "r"(dst), "l"(src) : "memory")
#define CP_COMMIT() asm volatile("cp.async.commit_group;" ::: "memory")
#define CP_WAIT1()  asm volatile("cp.async.wait_group 1;" ::: "memory")
#define CP_WAIT0()  asm volatile("cp.async.wait_group 0;" ::: "memory")

__device__ __forceinline__ void mma8(float c[4], const uint32_t a[4], const uint32_t b[2]) {
    asm volatile(
        "mma.sync.aligned.m16n8k8.row.col.f32.tf32.tf32.f32 "
        "{%0,%1,%2,%3}, {%4,%5,%6,%7}, {%8,%9}, {%0,%1,%2,%3};"
        : "+f"(c[0]), "+f"(c[1]), "+f"(c[2]), "+f"(c[3])
        : "r"(a[0]), "r"(a[1]), "r"(a[2]), "r"(a[3]), "r"(b[0]), "r"(b[1]));
}

// ---------------- LayerNorm: writes tf32 hi + fp32 residual --------------------
__global__ void ln_kernel(const float* __restrict__ x,
                          const float* __restrict__ gam,
                          const float* __restrict__ bet) {
    int row = blockIdx.x;
    const float* xr = x + (size_t)row * DIM;
    float s = 0.f, ss = 0.f;
    for (int i = threadIdx.x; i < DIM; i += 256) {
        float v = xr[i];
        s += v; ss += v * v;
    }
    __shared__ float sh[64];
    for (int o = 16; o; o >>= 1) {
        s  += __shfl_xor_sync(0xFFFFFFFFu, s,  o);
        ss += __shfl_xor_sync(0xFFFFFFFFu, ss, o);
    }
    int w = threadIdx.x >> 5, l = threadIdx.x & 31;
    if (l == 0) { sh[w] = s; sh[w + 32] = ss; }
    __syncthreads();
    if (w == 0) {
        s  = (l < 8) ? sh[l] : 0.f;
        ss = (l < 8) ? sh[l + 32] : 0.f;
        for (int o = 4; o; o >>= 1) {
            s  += __shfl_xor_sync(0xFFFFFFFFu, s,  o);
            ss += __shfl_xor_sync(0xFFFFFFFFu, ss, o);
        }
        if (l == 0) { sh[0] = s; sh[1] = ss; }
    }
    __syncthreads();
    float mu  = sh[0] * (1.0f / DIM);
    float var = sh[1] * (1.0f / DIM) - mu * mu;
    float r   = rsqrtf(var + EPSLN);
    for (int i = threadIdx.x; i < DIM; i += 256) {
        float v = (xr[i] - mu) * r * gam[i] + bet[i];
        float h = rtf32(v);
        g_xn [(size_t)row * DIM + i] = h;
        g_xnl[(size_t)row * DIM + i] = v - h;
    }
}

// ---------------- Router logits + softmax top-2 + gates + gap flag -------------
__global__ void router_kernel(const float* __restrict__ w2,
                              const float* __restrict__ b2) {
    int warp = threadIdx.x >> 5, lane = threadIdx.x & 31;
    int t = blockIdx.x * 8 + warp;
    const float* hrow = g_hr + (size_t)t * HHALF;
    float acc[NEXP] = {};
    for (int i = lane; i < HHALF; i += 32) {
        float v = hrow[i];
        const float4* wp = (const float4*)(w2 + i * NEXP);
        float4 w0 = __ldg(wp), w1 = __ldg(wp + 1);
        acc[0] += v * w0.x; acc[1] += v * w0.y; acc[2] += v * w0.z; acc[3] += v * w0.w;
        acc[4] += v * w1.x; acc[5] += v * w1.y; acc[6] += v * w1.z; acc[7] += v * w1.w;
    }
    for (int o = 16; o; o >>= 1)
#pragma unroll
        for (int e = 0; e < NEXP; e++)
            acc[e] += __shfl_xor_sync(0xFFFFFFFFu, acc[e], o);
    if (lane == 0) {
        float l[NEXP];
#pragma unroll
        for (int e = 0; e < NEXP; e++) l[e] = acc[e] + b2[e];
        int e1 = 0;
        for (int e = 1; e < NEXP; e++) if (l[e] > l[e1]) e1 = e;
        int e2 = -1;
        for (int e = 0; e < NEXP; e++) {
            if (e == e1) continue;
            if (e2 < 0 || l[e] > l[e2]) e2 = e;
        }
        int e3 = -1;
        for (int e = 0; e < NEXP; e++) {
            if (e == e1 || e == e2) continue;
            if (e3 < 0 || l[e] > l[e3]) e3 = e;
        }
        float ed  = expf(l[e2] - l[e1]);
        float inv = 1.f / (1.f + ed);
        g_e12[t] = e1 | (e2 << 8);
        g_g1[t] = inv;
        g_g2[t] = ed * inv;
        if (l[e2] - l[e3] < EPSG) {
            int pos = atomicAdd(&g_nflag, 1);
            g_flaglist[pos] = t;
        }
    }
}

// ---------------- exact fp32 repair of flagged tokens --------------------------
// 128 persistent CTAs, grid-stride over flag groups of 4. Worst-case bounded.
__global__ void __launch_bounds__(256) repair_kernel(
        const float* __restrict__ w1, const float* __restrict__ b1,
        const float* __restrict__ w2, const float* __restrict__ b2) {
    int nf = g_nflag;
    __shared__ float xs[4][DIM];
    __shared__ float slog[4][NEXP];
    int tid = threadIdx.x;

    for (int base = blockIdx.x * 4; base < nf; base += gridDim.x * 4) {
        int nv = nf - base; if (nv > 4) nv = 4;
        int toks[4];
#pragma unroll
        for (int j = 0; j < 4; j++)
            toks[j] = g_flaglist[(j < nv) ? base + j : base];

        __syncthreads();   // protect xs/slog reuse across iterations
        for (int j = 0; j < 4; j++) {
            const float* xh = g_xn  + (size_t)toks[j] * DIM;
            const float* xl = g_xnl + (size_t)toks[j] * DIM;
            for (int i = tid; i < DIM; i += 256) xs[j][i] = xh[i] + xl[i];
        }
        if (tid < 4 * NEXP) ((float*)slog)[tid] = b2[tid & (NEXP - 1)];
        __syncthreads();

        float pl[4][NEXP] = {};
        for (int c0 = 0; c0 < HHALF / 256; c0++) {
            int c = tid + c0 * 256;
            float a0 = b1[c], a1 = a0, a2 = a0, a3 = a0;
            const float* wc = w1 + c;
#pragma unroll 4
            for (int k = 0; k < DIM; k++) {
                float wv = __ldg(wc + (size_t)k * HHALF);
                a0 += xs[0][k] * wv;
                a1 += xs[1][k] * wv;
                a2 += xs[2][k] * wv;
                a3 += xs[3][k] * wv;
            }
            a0 = fmaxf(a0, 0.f); a1 = fmaxf(a1, 0.f);
            a2 = fmaxf(a2, 0.f); a3 = fmaxf(a3, 0.f);
#pragma unroll
            for (int e = 0; e < NEXP; e++) {
                float we = __ldg(w2 + (size_t)c * NEXP + e);
                pl[0][e] += a0 * we;
                pl[1][e] += a1 * we;
                pl[2][e] += a2 * we;
                pl[3][e] += a3 * we;
            }
        }
#pragma unroll
        for (int j = 0; j < 4; j++)
#pragma unroll
            for (int e = 0; e < NEXP; e++)
                atomicAdd(&slog[j][e], pl[j][e]);
        __syncthreads();

        if (tid < 4 && tid < nv) {
            int j = tid, t = toks[j];
            float l[NEXP];
#pragma unroll
            for (int e = 0; e < NEXP; e++) l[e] = slog[j][e];
            int e1 = 0;
            for (int e = 1; e < NEXP; e++) if (l[e] > l[e1]) e1 = e;
            int e2 = -1;
            for (int e = 0; e < NEXP; e++) {
                if (e == e1) continue;
                if (e2 < 0 || l[e] > l[e2]) e2 = e;
            }
            float ed  = expf(l[e2] - l[e1]);
            float inv = 1.f / (1.f + ed);
            g_e12[t] = e1 | (e2 << 8);
            g_g1[t] = inv;
            g_g2[t] = ed * inv;
        }
    }
}

__global__ void zero_cnt_kernel() {
    if (threadIdx.x < NEXP) g_cnt[threadIdx.x] = 0;
    if (threadIdx.x == 0) g_nflag = 0;
}
__global__ void count_kernel() {
    int t = blockIdx.x * 256 + threadIdx.x;
    int e12 = g_e12[t];
    atomicAdd(&g_cnt[e12 & 0xFF], 1);
    atomicAdd(&g_cnt[e12 >> 8], 1);
}
__global__ void scan_kernel() {
    if (threadIdx.x == 0) {
        int s = 0;
        for (int e = 0; e < NEXP; e++) { g_off[e] = s; s += g_cnt[e]; g_fill[e] = 0; }
    }
}
__global__ void place_kernel() {
    int t = blockIdx.x * 256 + threadIdx.x;
    int e12 = g_e12[t];
    int e1 = e12 & 0xFF, e2 = e12 >> 8;
    int s1 = g_off[e1] + atomicAdd(&g_fill[e1], 1);
    g_list[s1] = t; g_s1[t] = s1;
    int s2 = g_off[e2] + atomicAdd(&g_fill[e2], 1);
    g_list[s2] = t; g_s2[t] = s2;
}

// ---------------- final combine: out = x + g1*y[s1] + g2*y[s2] ------------------
__global__ void combine_kernel(const float* __restrict__ x, float* __restrict__ out) {
    int t = blockIdx.x;
    int s1 = g_s1[t], s2 = g_s2[t];
    float a = g_g1[t], b = g_g2[t];
    const float4* xr = (const float4*)(x   + (size_t)t  * DIM);
    const float4* y1 = (const float4*)(g_y + (size_t)s1 * DIM);
    const float4* y2 = (const float4*)(g_y + (size_t)s2 * DIM);
    float4* o = (float4*)(out + (size_t)t * DIM);
    int i = threadIdx.x;
    float4 xv = xr[i], v1 = y1[i], v2 = y2[i];
    float4 r;
    r.x = xv.x + a * v1.x + b * v2.x;
    r.y = xv.y + a * v1.y + b * v2.y;
    r.z = xv.z + a * v1.z + b * v2.z;
    r.w = xv.w + a * v1.w + b * v2.w;
    o[i] = r;
}

// ---------------- tf32 mma.sync GEMM (128x256 CTA, 64x64 warp tiles) ------------
// 3-stage cp.async pipeline, 1 CTA/SM. All modes single-pass tf32, BKC=32.
// MODE 0: g_hr = relu(xn @ r_w1 + b)                   M=16384 N=2048 K=1024
// MODE 1: g_h  = rtf32(relu(gather(xn) @ e_w1 + b))    M=cnt   N=4096 K=1024
// MODE 2: g_y  = g_h @ e_w2 + b   (compact rows)       M=cnt   N=1024 K=4096
template <int MODE>
__global__ void __launch_bounds__(256, 1)
moe_mma(const float* __restrict__ Wbase, const float* __restrict__ bias) {
    constexpr int Kd  = (MODE == 2) ? HID : DIM;
    constexpr int Nd  = (MODE == 0) ? HHALF : (MODE == 1) ? HID : DIM;
    constexpr int BKC = 32;
    constexpr int NC  = Kd / BKC;
    constexpr int AST = BKC + 4;
    constexpr int ASZ = BM * AST;
    constexpr int BSZ = BKC * BSTRD;
    constexpr int STG = ASZ + BSZ;
    constexpr int AJ  = BKC / 8;
    constexpr int BJ  = BKC / 4;

    int bm = blockIdx.y * BM, bn = blockIdx.x * BN;
    int e = 0, cnt = N_TOK, base = 0;
    if (MODE != 0) {
        e = blockIdx.z;
        cnt = g_cnt[e];
        if (bm >= cnt) return;
        base = g_off[e];
    }
    const float* Wh = (MODE == 0) ? Wbase
                    : (MODE == 1) ? Wbase + (size_t)e * DIM * HID
                                  : Wbase + (size_t)e * HID * DIM;
    const float* bp = bias + ((MODE == 0) ? 0 : (MODE == 1) ? e * HID : e * DIM);

    extern __shared__ float sm[];
    uint32_t smb = smem_u32(sm);

    int tid = threadIdx.x, lane = tid & 31, wid = tid >> 5;
    int wm = (wid >> 2) * 64, wn = (wid & 3) * 64;

    // ---- per-thread load slots ----
    const float* ah[AJ];
    const float* bh[BJ];
    uint32_t adst[AJ], bdst[BJ];
#pragma unroll
    for (int j = 0; j < AJ; j++) {
        int id = tid + 256 * j;
        int row = id / (BKC / 4), c4 = id % (BKC / 4);
        adst[j] = (uint32_t)row * (AST * 4) + c4 * 16;
        int r = bm + row;
        if (MODE == 1) {
            int rr = (r < cnt) ? r : cnt - 1;
            ah[j] = g_xn + (size_t)g_list[base + rr] * DIM + c4 * 4;
        } else if (MODE == 2) {
            int rr = (r < cnt) ? r : cnt - 1;
            ah[j] = g_h + (size_t)(base + rr) * HID + c4 * 4;
        } else {
            ah[j] = g_xn + (size_t)r * DIM + c4 * 4;
        }
    }
#pragma unroll
    for (int j = 0; j < BJ; j++) {
        int id = tid + 256 * j;
        int kr = id >> 6, c = id & 63;
        bdst[j] = (uint32_t)kr * (BSTRD * 4) + c * 16;
        bh[j] = Wh + (size_t)kr * Nd + bn + c * 4;
    }

    auto load = [&](int i, int st) {
        uint32_t s0 = smb + (uint32_t)st * STG * 4;
        uint32_t b0 = s0 + ASZ * 4;
        int ko = i * BKC;
        size_t bko = (size_t)ko * Nd;
#pragma unroll
        for (int j = 0; j < AJ; j++) CP16(s0 + adst[j], ah[j] + ko);
#pragma unroll
        for (int j = 0; j < BJ; j++) CP16(b0 + bdst[j], bh[j] + bko);
        CP_COMMIT();
    };

    float c[4][8][4] = {};
    load(0, 0);
    load(1, 1);

    int lr = lane >> 2, lc = lane & 3;
    for (int i = 0; i < NC; i++) {
        int st = i % 3;
        if (i + 2 < NC) { CP_WAIT1(); } else { CP_WAIT0(); }
        __syncthreads();
        if (i + 2 < NC) load(i + 2, (i + 2) % 3);

        const uint32_t* Au = (const uint32_t*)(sm + st * STG);
        const uint32_t* Bu = Au + ASZ;
#pragma unroll
        for (int ks = 0; ks < BKC / 8; ks++) {
            uint32_t a[4][4], b[8][2];
#pragma unroll
            for (int mt = 0; mt < 4; mt++) {
                const uint32_t* ap = Au + (wm + mt * 16 + lr) * AST + ks * 8 + lc;
                a[mt][0] = ap[0];
                a[mt][1] = ap[8 * AST];
                a[mt][2] = ap[4];
                a[mt][3] = ap[8 * AST + 4];
            }
#pragma unroll
            for (int nt = 0; nt < 8; nt++) {
                const uint32_t* bpp = Bu + (ks * 8 + lc) * BSTRD + wn + nt * 8 + lr;
                b[nt][0] = bpp[0];
                b[nt][1] = bpp[4 * BSTRD];
            }
#pragma unroll
            for (int mt = 0; mt < 4; mt++)
#pragma unroll
                for (int nt = 0; nt < 8; nt++)
                    mma8(c[mt][nt], a[mt], b[nt]);
        }
    }

    // ---------------- epilogue ----------------
#pragma unroll
    for (int mt = 0; mt < 4; mt++) {
#pragma unroll
        for (int half = 0; half < 2; half++) {
            int r = bm + wm + mt * 16 + lr + half * 8;
            if (MODE != 0 && r >= cnt) continue;
            float* row;
            if (MODE == 0)      row = g_hr + (size_t)r * HHALF;
            else if (MODE == 1) row = g_h  + (size_t)(base + r) * HID;
            else                row = g_y  + (size_t)(base + r) * DIM;
#pragma unroll
            for (int nt = 0; nt < 8; nt++) {
                int col = bn + wn + nt * 8 + lc * 2;
                float v0 = c[mt][nt][half * 2]     + bp[col];
                float v1 = c[mt][nt][half * 2 + 1] + bp[col + 1];
                float2 st2;
                if (MODE == 0) {
                    st2.x = fmaxf(v0, 0.f); st2.y = fmaxf(v1, 0.f);
                } else if (MODE == 1) {
                    st2.x = rtf32(fmaxf(v0, 0.f)); st2.y = rtf32(fmaxf(v1, 0.f));
                } else {
                    st2.x = v0; st2.y = v1;
                }
                *(float2*)(row + col) = st2;
            }
        }
    }
}

// ---------------- launch ---------------------------------------------------------
extern "C" void kernel_launch(void* const* d_in, const int* in_sizes, int n_in,
                              void* d_out, int out_size) {
    const float* x    = (const float*)d_in[0];
    const float* ln_g = (const float*)d_in[1];
    const float* ln_b = (const float*)d_in[2];
    const float* r_w1 = (const float*)d_in[3];
    const float* r_b1 = (const float*)d_in[4];
    const float* r_w2 = (const float*)d_in[5];
    const float* r_b2 = (const float*)d_in[6];
    const float* e_w1 = (const float*)d_in[7];
    const float* e_b1 = (const float*)d_in[8];
    const float* e_w2 = (const float*)d_in[9];
    const float* e_b2 = (const float*)d_in[10];
    float* out = (float*)d_out;

    const int SMEM_P = 3 * (BM * 36 + 32 * BSTRD) * 4;   // 156672

    static int configured = 0;
    if (!configured) {
        cudaFuncSetAttribute(moe_mma<0>, cudaFuncAttributeMaxDynamicSharedMemorySize, SMEM_P);
        cudaFuncSetAttribute(moe_mma<1>, cudaFuncAttributeMaxDynamicSharedMemorySize, SMEM_P);
        cudaFuncSetAttribute(moe_mma<2>, cudaFuncAttributeMaxDynamicSharedMemorySize, SMEM_P);
        configured = 1;
    }

    zero_cnt_kernel<<<1, 32>>>();
    ln_kernel<<<N_TOK, 256>>>(x, ln_g, ln_b);

    // router path: 1-pass tf32 GEMM -> logits + gap flags -> exact repair -> dispatch
    moe_mma<0><<<dim3(HHALF / BN, N_TOK / BM), 256, SMEM_P>>>(r_w1, r_b1);
    router_kernel<<<N_TOK / 8, 256>>>(r_w2, r_b2);
    repair_kernel<<<128, 256>>>(r_w1, r_b1, r_w2, r_b2);
    count_kernel<<<N_TOK / 256, 256>>>();
    scan_kernel<<<1, 32>>>();
    place_kernel<<<N_TOK / 256, 256>>>();

    // expert path (raw fp32 weights; HW truncates to tf32)
    moe_mma<1><<<dim3(HID / BN, N_TOK / BM, NEXP), 256, SMEM_P>>>(e_w1, e_b1);
    moe_mma<2><<<dim3(DIM / BN, N_TOK / BM, NEXP), 256, SMEM_P>>>(e_w2, e_b2);

    // out = x + g1*y1 + g2*y2
    combine_kernel<<<N_TOK, 256>>>(x, out);
}

// round 10
// speedup vs baseline: 1.1648x; 1.1287x over previous
#include <cuda_runtime.h>
#include <cstdint>

// Problem constants
#define N_TOK 16384
#define DIM   1024
#define HID   4096
#define HHALF 2048
#define NEXP  8
#define EPSLN 1e-5f

// CTA tile
#define BM 128
#define BN 256
#define BSTRD 264     // BN + 8 pad, conflict-free B frag reads

// ---------------- scratch (static device globals) -----------------------------
__device__ float g_xn [(size_t)N_TOK * DIM];
__device__ float g_xnl[(size_t)N_TOK * DIM];
__device__ float g_h  [(size_t)(2 * N_TOK) * HID];
__device__ float g_y  [(size_t)(2 * N_TOK) * DIM];
__device__ float g_w1h[(size_t)DIM * HHALF];
__device__ float g_w1l[(size_t)DIM * HHALF];
__device__ float g_part[(size_t)N_TOK * 64];   // per-token partial logits [t][gx][e]
__device__ int   g_cnt[NEXP];
__device__ int   g_off[NEXP];
__device__ int   g_fill[NEXP];
__device__ int   g_e12[N_TOK];
__device__ float g_g1[N_TOK];
__device__ float g_g2[N_TOK];
__device__ int   g_list[2 * N_TOK];
__device__ int   g_s1[N_TOK];
__device__ int   g_s2[N_TOK];

// ---------------- helpers ------------------------------------------------------
__device__ __forceinline__ uint32_t smem_u32(const void* p) {
    uint32_t a;
    asm("{ .reg .u64 t; cvta.to.shared.u64 t, %1; cvt.u32.u64 %0, t; }" : "=r"(a) : "l"(p));
    return a;
}
__device__ __forceinline__ float rtf32(float x) {
    float r; asm("cvt.rna.tf32.f32 %0, %1;" : "=f"(r) : "f"(x)); return r;
}
#define CP16(dst, src) \
    asm volatile("cp.async.cg.shared.global [%0], [%1], 16;" :: "r"(dst), "l"(src) : "memory")
#define CP_COMMIT() asm volatile("cp.async.commit_group;" ::: "memory")
#define CP_WAIT1()  asm volatile("cp.async.wait_group 1;" ::: "memory")
#define CP_WAIT0()  asm volatile("cp.async.wait_group 0;" ::: "memory")

__device__ __forceinline__ void mma8(float c[4], const uint32_t a[4], const uint32_t b[2]) {
    asm volatile(
        "mma.sync.aligned.m16n8k8.row.col.f32.tf32.tf32.f32 "
        "{%0,%1,%2,%3}, {%4,%5,%6,%7}, {%8,%9}, {%0,%1,%2,%3};"
        : "+f"(c[0]), "+f"(c[1]), "+f"(c[2]), "+f"(c[3])
        : "r"(a[0]), "r"(a[1]), "r"(a[2]), "r"(a[3]), "r"(b[0]), "r"(b[1]));
}

// ---------------- LayerNorm: writes tf32 hi + lo -------------------------------
__global__ void ln_kernel(const float* __restrict__ x,
                          const float* __restrict__ gam,
                          const float* __restrict__ bet) {
    int row = blockIdx.x;
    const float* xr = x + (size_t)row * DIM;
    float s = 0.f, ss = 0.f;
    for (int i = threadIdx.x; i < DIM; i += 256) {
        float v = xr[i];
        s += v; ss += v * v;
    }
    __shared__ float sh[64];
    for (int o = 16; o; o >>= 1) {
        s  += __shfl_xor_sync(0xFFFFFFFFu, s,  o);
        ss += __shfl_xor_sync(0xFFFFFFFFu, ss, o);
    }
    int w = threadIdx.x >> 5, l = threadIdx.x & 31;
    if (l == 0) { sh[w] = s; sh[w + 32] = ss; }
    __syncthreads();
    if (w == 0) {
        s  = (l < 8) ? sh[l] : 0.f;
        ss = (l < 8) ? sh[l + 32] : 0.f;
        for (int o = 4; o; o >>= 1) {
            s  += __shfl_xor_sync(0xFFFFFFFFu, s,  o);
            ss += __shfl_xor_sync(0xFFFFFFFFu, ss, o);
        }
        if (l == 0) { sh[0] = s; sh[1] = ss; }
    }
    __syncthreads();
    float mu  = sh[0] * (1.0f / DIM);
    float var = sh[1] * (1.0f / DIM) - mu * mu;
    float r   = rsqrtf(var + EPSLN);
    for (int i = threadIdx.x; i < DIM; i += 256) {
        float v = (xr[i] - mu) * r * gam[i] + bet[i];
        float h = rtf32(v);
        g_xn [(size_t)row * DIM + i] = h;
        g_xnl[(size_t)row * DIM + i] = rtf32(v - h);
    }
}

// ---------------- weight prep (router only) ------------------------------------
__global__ void split_copy(const float* __restrict__ in,
                           float* __restrict__ hi, float* __restrict__ lo) {
    size_t i = (size_t)(blockIdx.x * 256 + threadIdx.x) * 4;
    float4 v = *(const float4*)(in + i);
    float4 h, l;
    h.x = rtf32(v.x); l.x = rtf32(v.x - h.x);
    h.y = rtf32(v.y); l.y = rtf32(v.y - h.y);
    h.z = rtf32(v.z); l.z = rtf32(v.z - h.z);
    h.w = rtf32(v.w); l.w = rtf32(v.w - h.w);
    *(float4*)(hi + i) = h;
    *(float4*)(lo + i) = l;
}

// ---------------- Router: reduce partial logits -> top-2 + gates ---------------
__global__ void router_kernel(const float* __restrict__ b2) {
    int t = blockIdx.x * 256 + threadIdx.x;
    const float4* pp = (const float4*)(g_part + (size_t)t * 64);
    float l[NEXP];
#pragma unroll
    for (int e = 0; e < NEXP; e++) l[e] = b2[e];
#pragma unroll
    for (int gx = 0; gx < 8; gx++) {
        float4 p0 = pp[gx * 2], p1 = pp[gx * 2 + 1];
        l[0] += p0.x; l[1] += p0.y; l[2] += p0.z; l[3] += p0.w;
        l[4] += p1.x; l[5] += p1.y; l[6] += p1.z; l[7] += p1.w;
    }
    int e1 = 0;
    for (int e = 1; e < NEXP; e++) if (l[e] > l[e1]) e1 = e;
    int e2 = -1;
    for (int e = 0; e < NEXP; e++) {
        if (e == e1) continue;
        if (e2 < 0 || l[e] > l[e2]) e2 = e;
    }
    float ed  = expf(l[e2] - l[e1]);
    float inv = 1.f / (1.f + ed);
    g_e12[t] = e1 | (e2 << 8);
    g_g1[t] = inv;
    g_g2[t] = ed * inv;
    atomicAdd(&g_cnt[e1], 1);
    atomicAdd(&g_cnt[e2], 1);
}

__global__ void zero_cnt_kernel() {
    if (threadIdx.x < NEXP) g_cnt[threadIdx.x] = 0;
}
__global__ void scan_kernel() {
    if (threadIdx.x == 0) {
        int s = 0;
        for (int e = 0; e < NEXP; e++) { g_off[e] = s; s += g_cnt[e]; g_fill[e] = 0; }
    }
}
__global__ void place_kernel() {
    int t = blockIdx.x * 256 + threadIdx.x;
    if (t >= N_TOK) return;
    int e12 = g_e12[t];
    int e1 = e12 & 0xFF, e2 = e12 >> 8;
    int s1 = g_off[e1] + atomicAdd(&g_fill[e1], 1);
    g_list[s1] = t; g_s1[t] = s1;
    int s2 = g_off[e2] + atomicAdd(&g_fill[e2], 1);
    g_list[s2] = t; g_s2[t] = s2;
}

// ---------------- final combine: out = x + g1*y[s1] + g2*y[s2] ------------------
__global__ void combine_kernel(const float* __restrict__ x, float* __restrict__ out) {
    int t = blockIdx.x;
    int s1 = g_s1[t], s2 = g_s2[t];
    float a = g_g1[t], b = g_g2[t];
    const float4* xr = (const float4*)(x   + (size_t)t  * DIM);
    const float4* y1 = (const float4*)(g_y + (size_t)s1 * DIM);
    const float4* y2 = (const float4*)(g_y + (size_t)s2 * DIM);
    float4* o = (float4*)(out + (size_t)t * DIM);
    int i = threadIdx.x;
    float4 xv = xr[i], v1 = y1[i], v2 = y2[i];
    float4 r;
    r.x = xv.x + a * v1.x + b * v2.x;
    r.y = xv.y + a * v1.y + b * v2.y;
    r.z = xv.z + a * v1.z + b * v2.z;
    r.w = xv.w + a * v1.w + b * v2.w;
    o[i] = r;
}

// ---------------- tf32 mma.sync GEMM (128x256 CTA, 64x64 warp tiles) ------------
// 3-stage cp.async pipeline, 1 CTA/SM.
// MODE 0: split-tf32 xn @ r_w1; epilogue fuses relu + partial logits -> g_part
// MODE 1: g_h  = rtf32(relu(gather(xn) @ e_w1 + b))    M=cnt   N=4096 K=1024
// MODE 2: g_y  = g_h @ e_w2 + b   (compact rows)       M=cnt   N=1024 K=4096
template <int MODE>
__global__ void __launch_bounds__(256, 1)
moe_mma(const float* __restrict__ Wbase, const float* __restrict__ Wlbase,
        const float* __restrict__ bias, const float* __restrict__ w2) {
    constexpr bool SPLIT = (MODE == 0);
    constexpr int Kd  = (MODE == 2) ? HID : DIM;
    constexpr int Nd  = (MODE == 0) ? HHALF : (MODE == 1) ? HID : DIM;
    constexpr int BKC = SPLIT ? 16 : 32;
    constexpr int NC  = Kd / BKC;
    constexpr int AST = BKC + 4;
    constexpr int ASZ = BM * AST;
    constexpr int BSZ = BKC * BSTRD;
    constexpr int STG = (SPLIT ? 2 : 1) * (ASZ + BSZ);
    constexpr int AJ  = BKC / 8;
    constexpr int BJ  = BKC / 4;

    int bm = blockIdx.y * BM, bn = blockIdx.x * BN;
    int e = 0, cnt = N_TOK, base = 0;
    if (MODE != 0) {
        e = blockIdx.z;
        cnt = g_cnt[e];
        if (bm >= cnt) return;
        base = g_off[e];
    }
    const float* Wh = (MODE == 0) ? Wbase
                    : (MODE == 1) ? Wbase + (size_t)e * DIM * HID
                                  : Wbase + (size_t)e * HID * DIM;
    const float* Wl = Wlbase;
    const float* bp = bias + ((MODE == 0) ? 0 : (MODE == 1) ? e * HID : e * DIM);

    extern __shared__ float sm[];
    uint32_t smb = smem_u32(sm);

    int tid = threadIdx.x, lane = tid & 31, wid = tid >> 5;
    int wm = (wid >> 2) * 64, wn = (wid & 3) * 64;

    // MODE 0 extras: w2 tile (256x8) + partial-logit accumulator (128x8) in smem
    float* w2s  = sm + 3 * STG;
    float* slog = w2s + BN * NEXP;
    if (MODE == 0) {
        for (int i = tid; i < BN * NEXP; i += 256)
            w2s[i] = w2[(size_t)(bn + (i >> 3)) * NEXP + (i & 7)];
        for (int i = tid; i < BM * NEXP; i += 256)
            slog[i] = 0.f;
        // synced by the first __syncthreads in the main loop before use
    }

    // ---- per-thread load slots ----
    const float* ah[AJ];
    const float* al[AJ];
    const float* bh[BJ];
    const float* bl[BJ];
    uint32_t adst[AJ], bdst[BJ];
#pragma unroll
    for (int j = 0; j < AJ; j++) {
        int id = tid + 256 * j;
        int row = id / (BKC / 4), c4 = id % (BKC / 4);
        adst[j] = (uint32_t)row * (AST * 4) + c4 * 16;
        int r = bm + row;
        if (MODE == 1) {
            int rr = (r < cnt) ? r : cnt - 1;
            ah[j] = g_xn + (size_t)g_list[base + rr] * DIM + c4 * 4;
        } else if (MODE == 2) {
            int rr = (r < cnt) ? r : cnt - 1;
            ah[j] = g_h + (size_t)(base + rr) * HID + c4 * 4;
        } else {
            ah[j] = g_xn  + (size_t)r * DIM + c4 * 4;
            al[j] = g_xnl + (size_t)r * DIM + c4 * 4;
        }
    }
#pragma unroll
    for (int j = 0; j < BJ; j++) {
        int id = tid + 256 * j;
        int kr = id >> 6, c = id & 63;
        bdst[j] = (uint32_t)kr * (BSTRD * 4) + c * 16;
        bh[j] = Wh + (size_t)kr * Nd + bn + c * 4;
        if (SPLIT) bl[j] = Wl + (size_t)kr * Nd + bn + c * 4;
    }

    auto load = [&](int i, int st) {
        uint32_t s0 = smb + (uint32_t)st * STG * 4;
        uint32_t b0 = s0 + (SPLIT ? 2u : 1u) * ASZ * 4;
        int ko = i * BKC;
        size_t bko = (size_t)ko * Nd;
#pragma unroll
        for (int j = 0; j < AJ; j++) {
            CP16(s0 + adst[j], ah[j] + ko);
            if (SPLIT) CP16(s0 + ASZ * 4 + adst[j], al[j] + ko);
        }
#pragma unroll
        for (int j = 0; j < BJ; j++) {
            CP16(b0 + bdst[j], bh[j] + bko);
            if (SPLIT) CP16(b0 + BSZ * 4 + bdst[j], bl[j] + bko);
        }
        CP_COMMIT();
    };

    float c[4][8][4] = {};
    load(0, 0);
    load(1, 1);

    int lr = lane >> 2, lc = lane & 3;
    for (int i = 0; i < NC; i++) {
        int st = i % 3;
        if (i + 2 < NC) { CP_WAIT1(); } else { CP_WAIT0(); }
        __syncthreads();
        if (i + 2 < NC) load(i + 2, (i + 2) % 3);

        const uint32_t* Au = (const uint32_t*)(sm + st * STG);
        const uint32_t* Bu = Au + (SPLIT ? 2 : 1) * ASZ;
#pragma unroll
        for (int ks = 0; ks < BKC / 8; ks++) {
            uint32_t a[4][4], b[8][2];
#pragma unroll
            for (int mt = 0; mt < 4; mt++) {
                const uint32_t* ap = Au + (wm + mt * 16 + lr) * AST + ks * 8 + lc;
                a[mt][0] = ap[0];
                a[mt][1] = ap[8 * AST];
                a[mt][2] = ap[4];
                a[mt][3] = ap[8 * AST + 4];
            }
#pragma unroll
            for (int nt = 0; nt < 8; nt++) {
                const uint32_t* bpp = Bu + (ks * 8 + lc) * BSTRD + wn + nt * 8 + lr;
                b[nt][0] = bpp[0];
                b[nt][1] = bpp[4 * BSTRD];
            }
#pragma unroll
            for (int mt = 0; mt < 4; mt++)
#pragma unroll
                for (int nt = 0; nt < 8; nt++)
                    mma8(c[mt][nt], a[mt], b[nt]);
            if (SPLIT) {
                // hi * lo
                uint32_t t2[8][2];
#pragma unroll
                for (int nt = 0; nt < 8; nt++) {
                    const uint32_t* bpp = Bu + BSZ + (ks * 8 + lc) * BSTRD + wn + nt * 8 + lr;
                    t2[nt][0] = bpp[0];
                    t2[nt][1] = bpp[4 * BSTRD];
                }
#pragma unroll
                for (int mt = 0; mt < 4; mt++)
#pragma unroll
                    for (int nt = 0; nt < 8; nt++)
                        mma8(c[mt][nt], a[mt], t2[nt]);
                // lo * hi
                uint32_t a2[4][4];
#pragma unroll
                for (int mt = 0; mt < 4; mt++) {
                    const uint32_t* ap = Au + ASZ + (wm + mt * 16 + lr) * AST + ks * 8 + lc;
                    a2[mt][0] = ap[0];
                    a2[mt][1] = ap[8 * AST];
                    a2[mt][2] = ap[4];
                    a2[mt][3] = ap[8 * AST + 4];
                }
#pragma unroll
                for (int mt = 0; mt < 4; mt++)
#pragma unroll
                    for (int nt = 0; nt < 8; nt++)
                        mma8(c[mt][nt], a2[mt], b[nt]);
            }
        }
    }

    // ---------------- epilogue ----------------
    if (MODE == 0) {
        // fused: relu(hr + b1) projected onto w2 -> per-CTA partial logits
#pragma unroll
        for (int mt = 0; mt < 4; mt++) {
#pragma unroll
            for (int half = 0; half < 2; half++) {
                int row_l = wm + mt * 16 + lr + half * 8;   // local row 0..127
                float pe[NEXP] = {};
#pragma unroll
                for (int nt = 0; nt < 8; nt++) {
                    int cl = wn + nt * 8 + lc * 2;          // local col 0..255
                    float v0 = fmaxf(c[mt][nt][half * 2]     + bp[bn + cl],     0.f);
                    float v1 = fmaxf(c[mt][nt][half * 2 + 1] + bp[bn + cl + 1], 0.f);
                    const float* wr0 = w2s + cl * NEXP;
                    const float* wr1 = wr0 + NEXP;
#pragma unroll
                    for (int ee = 0; ee < NEXP; ee++)
                        pe[ee] += v0 * wr0[ee] + v1 * wr1[ee];
                }
#pragma unroll
                for (int ee = 0; ee < NEXP; ee++)
                    atomicAdd(&slog[row_l * NEXP + ee], pe[ee]);
            }
        }
        __syncthreads();
        for (int i = tid; i < BM * NEXP; i += 256) {
            int row = i >> 3, ee = i & 7;
            g_part[(size_t)(bm + row) * 64 + blockIdx.x * 8 + ee] = slog[i];
        }
        return;
    }

#pragma unroll
    for (int mt = 0; mt < 4; mt++) {
#pragma unroll
        for (int half = 0; half < 2; half++) {
            int r = bm + wm + mt * 16 + lr + half * 8;
            if (r >= cnt) continue;
            float* row;
            if (MODE == 1) row = g_h + (size_t)(base + r) * HID;
            else           row = g_y + (size_t)(base + r) * DIM;
#pragma unroll
            for (int nt = 0; nt < 8; nt++) {
                int col = bn + wn + nt * 8 + lc * 2;
                float v0 = c[mt][nt][half * 2]     + bp[col];
                float v1 = c[mt][nt][half * 2 + 1] + bp[col + 1];
                float2 st2;
                if (MODE == 1) {
                    st2.x = rtf32(fmaxf(v0, 0.f)); st2.y = rtf32(fmaxf(v1, 0.f));
                } else {
                    st2.x = v0; st2.y = v1;
                }
                *(float2*)(row + col) = st2;
            }
        }
    }
}

// ---------------- launch ---------------------------------------------------------
extern "C" void kernel_launch(void* const* d_in, const int* in_sizes, int n_in,
                              void* d_out, int out_size) {
    const float* x    = (const float*)d_in[0];
    const float* ln_g = (const float*)d_in[1];
    const float* ln_b = (const float*)d_in[2];
    const float* r_w1 = (const float*)d_in[3];
    const float* r_b1 = (const float*)d_in[4];
    const float* r_w2 = (const float*)d_in[5];
    const float* r_b2 = (const float*)d_in[6];
    const float* e_w1 = (const float*)d_in[7];
    const float* e_b1 = (const float*)d_in[8];
    const float* e_w2 = (const float*)d_in[9];
    const float* e_b2 = (const float*)d_in[10];
    float* out = (float*)d_out;

    // smem sizes (3-stage)
    const int SMEM_P = 3 * (BM * 36 + 32 * BSTRD) * 4;             // plain: 156672
    const int SMEM_S = 3 * (2 * (BM * 20) + 2 * (16 * BSTRD)) * 4  // split stages
                       + (BN * NEXP + BM * NEXP) * 4;              // + w2 tile + slog
                                                                   // = 162816 + 12288

    static int configured = 0;
    if (!configured) {
        cudaFuncSetAttribute(moe_mma<0>, cudaFuncAttributeMaxDynamicSharedMemorySize, SMEM_S);
        cudaFuncSetAttribute(moe_mma<1>, cudaFuncAttributeMaxDynamicSharedMemorySize, SMEM_P);
        cudaFuncSetAttribute(moe_mma<2>, cudaFuncAttributeMaxDynamicSharedMemorySize, SMEM_P);
        configured = 1;
    }

    zero_cnt_kernel<<<1, 32>>>();
    ln_kernel<<<N_TOK, 256>>>(x, ln_g, ln_b);

    // router weight split (tf32 hi/lo)
    float *w1h, *w1l;
    cudaGetSymbolAddress((void**)&w1h, g_w1h);
    cudaGetSymbolAddress((void**)&w1l, g_w1l);
    split_copy<<<(DIM * HHALF / 4) / 256, 256>>>(r_w1, w1h, w1l);

    // router path: split-tf32 GEMM with fused logit partials -> reduce -> dispatch
    moe_mma<0><<<dim3(HHALF / BN, N_TOK / BM), 256, SMEM_S>>>(w1h, w1l, r_b1, r_w2);
    router_kernel<<<N_TOK / 256, 256>>>(r_b2);
    scan_kernel<<<1, 32>>>();
    place_kernel<<<N_TOK / 256, 256>>>();

    // expert path (raw fp32 weights; HW truncates to tf32)
    moe_mma<1><<<dim3(HID / BN, N_TOK / BM, NEXP), 256, SMEM_P>>>(e_w1, nullptr, e_b1, nullptr);
    moe_mma<2><<<dim3(DIM / BN, N_TOK / BM, NEXP), 256, SMEM_P>>>(e_w2, nullptr, e_b2, nullptr);

    // out = x + g1*y1 + g2*y2
    combine_kernel<<<N_TOK, 256>>>(x, out);
}

// round 11
// speedup vs baseline: 1.7513x; 1.5035x over previous
#include <cuda_runtime.h>
#include <cuda_fp16.h>
#include <cstdint>

// Problem constants
#define N_TOK 16384
#define DIM   1024
#define HID   4096
#define HHALF 2048
#define NEXP  8
#define EPSLN 1e-5f

// CTA tile
#define BM 128
#define BN 256
#define BSTRD 264

// ---------------- scratch -------------------------------------------------------
__device__ float    g_xn [(size_t)N_TOK * DIM];          // tf32 hi (router)
__device__ float    g_xnl[(size_t)N_TOK * DIM];          // tf32 lo (router)
__device__ __half   g_xnh[(size_t)N_TOK * DIM];          // fp16 xn (experts)
__device__ float    g_hr [(size_t)N_TOK * HHALF];
__device__ uint32_t g_hh [(size_t)(2 * N_TOK) * (HID / 2)];  // fp16 h, half2-packed
__device__ float    g_y  [(size_t)(2 * N_TOK) * DIM];
__device__ float    g_w1h[(size_t)DIM * HHALF];
__device__ float    g_w1l[(size_t)DIM * HHALF];
__device__ uint32_t g_ew1p[(size_t)NEXP * (DIM / 2) * HID];  // fp16 packed [e][k/2][n]
__device__ uint32_t g_ew2p[(size_t)NEXP * (HID / 2) * DIM];
__device__ int   g_cnt[NEXP];
__device__ int   g_off[NEXP];
__device__ int   g_fill[NEXP];
__device__ int   g_e12[N_TOK];
__device__ float g_g1[N_TOK];
__device__ float g_g2[N_TOK];
__device__ int   g_list[2 * N_TOK];
__device__ int   g_s1[N_TOK];
__device__ int   g_s2[N_TOK];

// ---------------- helpers -------------------------------------------------------
__device__ __forceinline__ uint32_t smem_u32(const void* p) {
    uint32_t a;
    asm("{ .reg .u64 t; cvta.to.shared.u64 t, %1; cvt.u32.u64 %0, t; }" : "=r"(a) : "l"(p));
    return a;
}
__device__ __forceinline__ float rtf32(float x) {
    float r; asm("cvt.rna.tf32.f32 %0, %1;" : "=f"(r) : "f"(x)); return r;
}
#define CP16(dst, src) \
    asm volatile("cp.async.cg.shared.global [%0], [%1], 16;" :: "r"(dst), "l"(src) : "memory")
#define CP_COMMIT() asm volatile("cp.async.commit_group;" ::: "memory")
#define CP_WAIT1()  asm volatile("cp.async.wait_group 1;" ::: "memory")
#define CP_WAIT0()  asm volatile("cp.async.wait_group 0;" ::: "memory")

__device__ __forceinline__ void mma8(float c[4], const uint32_t a[4], const uint32_t b[2]) {
    asm volatile(
        "mma.sync.aligned.m16n8k8.row.col.f32.tf32.tf32.f32 "
        "{%0,%1,%2,%3}, {%4,%5,%6,%7}, {%8,%9}, {%0,%1,%2,%3};"
        : "+f"(c[0]), "+f"(c[1]), "+f"(c[2]), "+f"(c[3])
        : "r"(a[0]), "r"(a[1]), "r"(a[2]), "r"(a[3]), "r"(b[0]), "r"(b[1]));
}
__device__ __forceinline__ void mma16(float c[4], const uint32_t a[4], const uint32_t b[2]) {
    asm volatile(
        "mma.sync.aligned.m16n8k16.row.col.f32.f16.f16.f32 "
        "{%0,%1,%2,%3}, {%4,%5,%6,%7}, {%8,%9}, {%0,%1,%2,%3};"
        : "+f"(c[0]), "+f"(c[1]), "+f"(c[2]), "+f"(c[3])
        : "r"(a[0]), "r"(a[1]), "r"(a[2]), "r"(a[3]), "r"(b[0]), "r"(b[1]));
}

// ---------------- LayerNorm: tf32 hi/lo + fp16 -----------------------------------
__global__ void ln_kernel(const float* __restrict__ x,
                          const float* __restrict__ gam,
                          const float* __restrict__ bet) {
    int row = blockIdx.x;
    const float* xr = x + (size_t)row * DIM;
    float s = 0.f, ss = 0.f;
    for (int i = threadIdx.x; i < DIM; i += 256) {
        float v = xr[i];
        s += v; ss += v * v;
    }
    __shared__ float sh[64];
    for (int o = 16; o; o >>= 1) {
        s  += __shfl_xor_sync(0xFFFFFFFFu, s,  o);
        ss += __shfl_xor_sync(0xFFFFFFFFu, ss, o);
    }
    int w = threadIdx.x >> 5, l = threadIdx.x & 31;
    if (l == 0) { sh[w] = s; sh[w + 32] = ss; }
    __syncthreads();
    if (w == 0) {
        s  = (l < 8) ? sh[l] : 0.f;
        ss = (l < 8) ? sh[l + 32] : 0.f;
        for (int o = 4; o; o >>= 1) {
            s  += __shfl_xor_sync(0xFFFFFFFFu, s,  o);
            ss += __shfl_xor_sync(0xFFFFFFFFu, ss, o);
        }
        if (l == 0) { sh[0] = s; sh[1] = ss; }
    }
    __syncthreads();
    float mu  = sh[0] * (1.0f / DIM);
    float var = sh[1] * (1.0f / DIM) - mu * mu;
    float r   = rsqrtf(var + EPSLN);
    for (int i = threadIdx.x; i < DIM; i += 256) {
        float v = (xr[i] - mu) * r * gam[i] + bet[i];
        float h = rtf32(v);
        g_xn [(size_t)row * DIM + i] = h;
        g_xnl[(size_t)row * DIM + i] = rtf32(v - h);
        g_xnh[(size_t)row * DIM + i] = __float2half_rn(v);
    }
}

// ---------------- weight prep ----------------------------------------------------
__global__ void split_copy(const float* __restrict__ in,
                           float* __restrict__ hi, float* __restrict__ lo) {
    size_t i = (size_t)(blockIdx.x * 256 + threadIdx.x) * 4;
    float4 v = *(const float4*)(in + i);
    float4 h, l;
    h.x = rtf32(v.x); l.x = rtf32(v.x - h.x);
    h.y = rtf32(v.y); l.y = rtf32(v.y - h.y);
    h.z = rtf32(v.z); l.z = rtf32(v.z - h.z);
    h.w = rtf32(v.w); l.w = rtf32(v.w - h.w);
    *(float4*)(hi + i) = h;
    *(float4*)(lo + i) = l;
}

// pack fp32 [R][N] -> fp16 half2 [R/2][N] u32 (low = even row)
__global__ void packw(const float* __restrict__ in, uint32_t* __restrict__ out,
                      int ncols) {
    size_t idx = (size_t)blockIdx.x * 256 + threadIdx.x;   // one uint4 each
    size_t n4 = (size_t)ncols / 4;
    size_t r2 = idx / n4;
    size_t c  = (idx % n4) * 4;
    const float4 v0 = *(const float4*)(in + (2 * r2) * ncols + c);
    const float4 v1 = *(const float4*)(in + (2 * r2 + 1) * ncols + c);
    uint4 o;
    __half2 t;
    t = __floats2half2_rn(v0.x, v1.x); o.x = *(uint32_t*)&t;
    t = __floats2half2_rn(v0.y, v1.y); o.y = *(uint32_t*)&t;
    t = __floats2half2_rn(v0.z, v1.z); o.z = *(uint32_t*)&t;
    t = __floats2half2_rn(v0.w, v1.w); o.w = *(uint32_t*)&t;
    *(uint4*)(out + r2 * ncols + c) = o;
}

// ---------------- Router logits + softmax top-2 + gates --------------------------
__global__ void router_kernel(const float* __restrict__ w2,
                              const float* __restrict__ b2) {
    int warp = threadIdx.x >> 5, lane = threadIdx.x & 31;
    int t = blockIdx.x * 8 + warp;
    const float* hrow = g_hr + (size_t)t * HHALF;
    float acc[NEXP] = {};
    for (int i = lane; i < HHALF; i += 32) {
        float v = hrow[i];
        const float4* wp = (const float4*)(w2 + i * NEXP);
        float4 w0 = __ldg(wp), w1 = __ldg(wp + 1);
        acc[0] += v * w0.x; acc[1] += v * w0.y; acc[2] += v * w0.z; acc[3] += v * w0.w;
        acc[4] += v * w1.x; acc[5] += v * w1.y; acc[6] += v * w1.z; acc[7] += v * w1.w;
    }
    for (int o = 16; o; o >>= 1)
#pragma unroll
        for (int e = 0; e < NEXP; e++)
            acc[e] += __shfl_xor_sync(0xFFFFFFFFu, acc[e], o);
    if (lane == 0) {
        float l[NEXP];
#pragma unroll
        for (int e = 0; e < NEXP; e++) l[e] = acc[e] + b2[e];
        int e1 = 0;
        for (int e = 1; e < NEXP; e++) if (l[e] > l[e1]) e1 = e;
        int e2 = -1;
        for (int e = 0; e < NEXP; e++) {
            if (e == e1) continue;
            if (e2 < 0 || l[e] > l[e2]) e2 = e;
        }
        float ed  = expf(l[e2] - l[e1]);
        float inv = 1.f / (1.f + ed);
        g_e12[t] = e1 | (e2 << 8);
        g_g1[t] = inv;
        g_g2[t] = ed * inv;
        atomicAdd(&g_cnt[e1], 1);
        atomicAdd(&g_cnt[e2], 1);
    }
}

__global__ void zero_cnt_kernel() {
    if (threadIdx.x < NEXP) g_cnt[threadIdx.x] = 0;
}
__global__ void scan_kernel() {
    if (threadIdx.x == 0) {
        int s = 0;
        for (int e = 0; e < NEXP; e++) { g_off[e] = s; s += g_cnt[e]; g_fill[e] = 0; }
    }
}
__global__ void place_kernel() {
    int t = blockIdx.x * 256 + threadIdx.x;
    if (t >= N_TOK) return;
    int e12 = g_e12[t];
    int e1 = e12 & 0xFF, e2 = e12 >> 8;
    int s1 = g_off[e1] + atomicAdd(&g_fill[e1], 1);
    g_list[s1] = t; g_s1[t] = s1;
    int s2 = g_off[e2] + atomicAdd(&g_fill[e2], 1);
    g_list[s2] = t; g_s2[t] = s2;
}

// ---------------- final combine --------------------------------------------------
__global__ void combine_kernel(const float* __restrict__ x, float* __restrict__ out) {
    int t = blockIdx.x;
    int s1 = g_s1[t], s2 = g_s2[t];
    float a = g_g1[t], b = g_g2[t];
    const float4* xr = (const float4*)(x   + (size_t)t  * DIM);
    const float4* y1 = (const float4*)(g_y + (size_t)s1 * DIM);
    const float4* y2 = (const float4*)(g_y + (size_t)s2 * DIM);
    float4* o = (float4*)(out + (size_t)t * DIM);
    int i = threadIdx.x;
    float4 xv = xr[i], v1 = y1[i], v2 = y2[i];
    float4 r;
    r.x = xv.x + a * v1.x + b * v2.x;
    r.y = xv.y + a * v1.y + b * v2.y;
    r.z = xv.z + a * v1.z + b * v2.z;
    r.w = xv.w + a * v1.w + b * v2.w;
    o[i] = r;
}

// ---------------- Router GEMM: split-tf32, 128x256 CTA, 64x64 warp tiles ---------
// g_hr = relu((xn_hi+xn_lo) @ (w1_hi+w1_lo) + b1), M=16384 N=2048 K=1024
__global__ void __launch_bounds__(256, 1)
gemm_router(const float* __restrict__ Wh, const float* __restrict__ Wl,
            const float* __restrict__ bias) {
    constexpr int BKC = 16;
    constexpr int NC  = DIM / BKC;
    constexpr int AST = BKC + 4;
    constexpr int ASZ = BM * AST;
    constexpr int BSZ = BKC * BSTRD;
    constexpr int STG = 2 * (ASZ + BSZ);

    int bm = blockIdx.y * BM, bn = blockIdx.x * BN;
    extern __shared__ float sm[];
    uint32_t smb = smem_u32(sm);
    int tid = threadIdx.x, lane = tid & 31, wid = tid >> 5;
    int wm = (wid >> 2) * 64, wn = (wid & 3) * 64;

    const float* ah[2];
    const float* al[2];
    const float* bh[4];
    const float* bl[4];
    uint32_t adst[2], bdst[4];
#pragma unroll
    for (int j = 0; j < 2; j++) {
        int id = tid + 256 * j;
        int row = id / 4, c4 = id % 4;
        adst[j] = (uint32_t)row * (AST * 4) + c4 * 16;
        int r = bm + row;
        ah[j] = g_xn  + (size_t)r * DIM + c4 * 4;
        al[j] = g_xnl + (size_t)r * DIM + c4 * 4;
    }
#pragma unroll
    for (int j = 0; j < 4; j++) {
        int id = tid + 256 * j;
        int kr = id >> 6, c = id & 63;
        bdst[j] = (uint32_t)kr * (BSTRD * 4) + c * 16;
        bh[j] = Wh + (size_t)kr * HHALF + bn + c * 4;
        bl[j] = Wl + (size_t)kr * HHALF + bn + c * 4;
    }

    auto load = [&](int i, int st) {
        uint32_t s0 = smb + (uint32_t)st * STG * 4;
        uint32_t b0 = s0 + 2u * ASZ * 4;
        int ko = i * BKC;
        size_t bko = (size_t)ko * HHALF;
#pragma unroll
        for (int j = 0; j < 2; j++) {
            CP16(s0 + adst[j], ah[j] + ko);
            CP16(s0 + ASZ * 4 + adst[j], al[j] + ko);
        }
#pragma unroll
        for (int j = 0; j < 4; j++) {
            CP16(b0 + bdst[j], bh[j] + bko);
            CP16(b0 + BSZ * 4 + bdst[j], bl[j] + bko);
        }
        CP_COMMIT();
    };

    float c[4][8][4] = {};
    load(0, 0);
    load(1, 1);

    int lr = lane >> 2, lc = lane & 3;
    for (int i = 0; i < NC; i++) {
        int st = i % 3;
        if (i + 2 < NC) { CP_WAIT1(); } else { CP_WAIT0(); }
        __syncthreads();
        if (i + 2 < NC) load(i + 2, (i + 2) % 3);

        const uint32_t* Au = (const uint32_t*)(sm + st * STG);
        const uint32_t* Bu = Au + 2 * ASZ;
#pragma unroll
        for (int ks = 0; ks < 2; ks++) {
            uint32_t a[4][4], b[8][2];
#pragma unroll
            for (int mt = 0; mt < 4; mt++) {
                const uint32_t* ap = Au + (wm + mt * 16 + lr) * AST + ks * 8 + lc;
                a[mt][0] = ap[0];
                a[mt][1] = ap[8 * AST];
                a[mt][2] = ap[4];
                a[mt][3] = ap[8 * AST + 4];
            }
#pragma unroll
            for (int nt = 0; nt < 8; nt++) {
                const uint32_t* bpp = Bu + (ks * 8 + lc) * BSTRD + wn + nt * 8 + lr;
                b[nt][0] = bpp[0];
                b[nt][1] = bpp[4 * BSTRD];
            }
#pragma unroll
            for (int mt = 0; mt < 4; mt++)
#pragma unroll
                for (int nt = 0; nt < 8; nt++)
                    mma8(c[mt][nt], a[mt], b[nt]);
            // hi * lo
            uint32_t t2[8][2];
#pragma unroll
            for (int nt = 0; nt < 8; nt++) {
                const uint32_t* bpp = Bu + BSZ + (ks * 8 + lc) * BSTRD + wn + nt * 8 + lr;
                t2[nt][0] = bpp[0];
                t2[nt][1] = bpp[4 * BSTRD];
            }
#pragma unroll
            for (int mt = 0; mt < 4; mt++)
#pragma unroll
                for (int nt = 0; nt < 8; nt++)
                    mma8(c[mt][nt], a[mt], t2[nt]);
            // lo * hi
            uint32_t a2[4][4];
#pragma unroll
            for (int mt = 0; mt < 4; mt++) {
                const uint32_t* ap = Au + ASZ + (wm + mt * 16 + lr) * AST + ks * 8 + lc;
                a2[mt][0] = ap[0];
                a2[mt][1] = ap[8 * AST];
                a2[mt][2] = ap[4];
                a2[mt][3] = ap[8 * AST + 4];
            }
#pragma unroll
            for (int mt = 0; mt < 4; mt++)
#pragma unroll
                for (int nt = 0; nt < 8; nt++)
                    mma8(c[mt][nt], a2[mt], b[nt]);
        }
    }

#pragma unroll
    for (int mt = 0; mt < 4; mt++) {
#pragma unroll
        for (int half = 0; half < 2; half++) {
            int r = bm + wm + mt * 16 + lr + half * 8;
            float* row = g_hr + (size_t)r * HHALF;
#pragma unroll
            for (int nt = 0; nt < 8; nt++) {
                int col = bn + wn + nt * 8 + lc * 2;
                float v0 = c[mt][nt][half * 2]     + bias[col];
                float v1 = c[mt][nt][half * 2 + 1] + bias[col + 1];
                float2 st2;
                st2.x = fmaxf(v0, 0.f); st2.y = fmaxf(v1, 0.f);
                *(float2*)(row + col) = st2;
            }
        }
    }
}

// ---------------- Expert GEMMs: fp16 m16n8k16, BKC=64, 3-stage -------------------
// MODE 1: g_hh = fp16(relu(gather(xnh) @ e_w1 + b1))   M=cnt N=4096 K=1024
// MODE 2: g_y  = g_hh @ e_w2 + b2 (fp32 out)           M=cnt N=1024 K=4096
template <int MODE>
__global__ void __launch_bounds__(256, 1)
moe_mma16(const uint32_t* __restrict__ Wp, const float* __restrict__ bias) {
    constexpr int Kd   = (MODE == 2) ? HID : DIM;
    constexpr int Nd   = (MODE == 1) ? HID : DIM;
    constexpr int BKC  = 64;               // k (fp16 elems) per chunk
    constexpr int KU   = BKC / 2;          // 32 u32 per A row / B k2-rows
    constexpr int NC   = Kd / BKC;
    constexpr int AST  = KU + 4;           // 36 u32
    constexpr int ASZ  = BM * AST;
    constexpr int BST2 = BN + 8;           // 264 u32
    constexpr int BSZ  = KU * BST2;
    constexpr int STG  = ASZ + BSZ;        // u32

    int bm = blockIdx.y * BM, bn = blockIdx.x * BN;
    int e = blockIdx.z;
    int cnt = g_cnt[e];
    if (bm >= cnt) return;
    int base = g_off[e];
    const uint32_t* W = Wp + (size_t)e * (Kd / 2) * Nd;
    const float* bp = bias + e * Nd;

    extern __shared__ uint32_t smu[];
    uint32_t smb = smem_u32(smu);
    int tid = threadIdx.x, lane = tid & 31, wid = tid >> 5;
    int wm = (wid >> 2) * 64, wn = (wid & 3) * 64;

    // A: 128 rows x 32 u32 -> 4 CP16/thread
    const uint32_t* ah[4];
    uint32_t adst[4];
#pragma unroll
    for (int j = 0; j < 4; j++) {
        int id = tid + 256 * j;
        int row = id >> 3, c4 = id & 7;
        adst[j] = (uint32_t)row * (AST * 4) + c4 * 16;
        int r = bm + row; if (r >= cnt) r = cnt - 1;
        if (MODE == 1) {
            int tok = g_list[base + r];
            ah[j] = (const uint32_t*)g_xnh + (size_t)tok * (DIM / 2) + c4 * 4;
        } else {
            ah[j] = g_hh + (size_t)(base + r) * (HID / 2) + c4 * 4;
        }
    }
    // B: 32 k2-rows x 256 u32 -> 8 CP16/thread
    const uint32_t* bh[8];
    uint32_t bdst[8];
#pragma unroll
    for (int j = 0; j < 8; j++) {
        int id = tid + 256 * j;
        int kr = id >> 6, c = id & 63;
        bdst[j] = (uint32_t)kr * (BST2 * 4) + c * 16;
        bh[j] = W + (size_t)kr * Nd + bn + c * 4;
    }

    auto load = [&](int i, int st) {
        uint32_t s0 = smb + (uint32_t)st * STG * 4;
        uint32_t b0 = s0 + ASZ * 4;
        int ko = i * KU;                    // u32 offset along k for A
        size_t bko = (size_t)(i * KU) * Nd; // u32 offset for B rows
#pragma unroll
        for (int j = 0; j < 4; j++) CP16(s0 + adst[j], ah[j] + ko);
#pragma unroll
        for (int j = 0; j < 8; j++) CP16(b0 + bdst[j], bh[j] + bko);
        CP_COMMIT();
    };

    float c[4][8][4] = {};
    load(0, 0);
    load(1, 1);

    int lr = lane >> 2, lc = lane & 3;
    for (int i = 0; i < NC; i++) {
        int st = i % 3;
        if (i + 2 < NC) { CP_WAIT1(); } else { CP_WAIT0(); }
        __syncthreads();
        if (i + 2 < NC) load(i + 2, (i + 2) % 3);

        const uint32_t* Au = smu + st * STG;
        const uint32_t* Bu = Au + ASZ;
#pragma unroll
        for (int ks = 0; ks < 4; ks++) {       // 4 x k16 steps per chunk
            uint32_t a[4][4], b[8][2];
#pragma unroll
            for (int mt = 0; mt < 4; mt++) {
                const uint32_t* ap = Au + (wm + mt * 16 + lr) * AST + ks * 8 + lc;
                a[mt][0] = ap[0];
                a[mt][1] = ap[8 * AST];
                a[mt][2] = ap[4];
                a[mt][3] = ap[8 * AST + 4];
            }
#pragma unroll
            for (int nt = 0; nt < 8; nt++) {
                const uint32_t* bpp = Bu + (ks * 8 + lc) * BST2 + wn + nt * 8 + lr;
                b[nt][0] = bpp[0];
                b[nt][1] = bpp[4 * BST2];
            }
#pragma unroll
            for (int mt = 0; mt < 4; mt++)
#pragma unroll
                for (int nt = 0; nt < 8; nt++)
                    mma16(c[mt][nt], a[mt], b[nt]);
        }
    }

    // ---------------- epilogue ----------------
#pragma unroll
    for (int mt = 0; mt < 4; mt++) {
#pragma unroll
        for (int half = 0; half < 2; half++) {
            int r = bm + wm + mt * 16 + lr + half * 8;
            if (r >= cnt) continue;
            if (MODE == 1) {
                uint32_t* row = g_hh + (size_t)(base + r) * (HID / 2);
#pragma unroll
                for (int nt = 0; nt < 8; nt++) {
                    int col = bn + wn + nt * 8 + lc * 2;
                    float v0 = fmaxf(c[mt][nt][half * 2]     + bp[col],     0.f);
                    float v1 = fmaxf(c[mt][nt][half * 2 + 1] + bp[col + 1], 0.f);
                    __half2 hv = __floats2half2_rn(v0, v1);
                    row[col / 2] = *(uint32_t*)&hv;
                }
            } else {
                float* row = g_y + (size_t)(base + r) * DIM;
#pragma unroll
                for (int nt = 0; nt < 8; nt++) {
                    int col = bn + wn + nt * 8 + lc * 2;
                    float2 st2;
                    st2.x = c[mt][nt][half * 2]     + bp[col];
                    st2.y = c[mt][nt][half * 2 + 1] + bp[col + 1];
                    *(float2*)(row + col) = st2;
                }
            }
        }
    }
}

// ---------------- launch ---------------------------------------------------------
extern "C" void kernel_launch(void* const* d_in, const int* in_sizes, int n_in,
                              void* d_out, int out_size) {
    const float* x    = (const float*)d_in[0];
    const float* ln_g = (const float*)d_in[1];
    const float* ln_b = (const float*)d_in[2];
    const float* r_w1 = (const float*)d_in[3];
    const float* r_b1 = (const float*)d_in[4];
    const float* r_w2 = (const float*)d_in[5];
    const float* r_b2 = (const float*)d_in[6];
    const float* e_w1 = (const float*)d_in[7];
    const float* e_b1 = (const float*)d_in[8];
    const float* e_w2 = (const float*)d_in[9];
    const float* e_b2 = (const float*)d_in[10];
    float* out = (float*)d_out;

    // smem: router split 3x(2*(128*20)+2*(16*264))*4 = 162816
    //       fp16 GEMM   3x(128*36 + 32*264)*4       = 156672
    const int SMEM_R = 3 * (2 * (BM * 20) + 2 * (16 * BSTRD)) * 4;
    const int SMEM_H = 3 * (BM * 36 + 32 * BSTRD) * 4;

    static int configured = 0;
    if (!configured) {
        cudaFuncSetAttribute(gemm_router, cudaFuncAttributeMaxDynamicSharedMemorySize, SMEM_R);
        cudaFuncSetAttribute(moe_mma16<1>, cudaFuncAttributeMaxDynamicSharedMemorySize, SMEM_H);
        cudaFuncSetAttribute(moe_mma16<2>, cudaFuncAttributeMaxDynamicSharedMemorySize, SMEM_H);
        configured = 1;
    }

    zero_cnt_kernel<<<1, 32>>>();
    ln_kernel<<<N_TOK, 256>>>(x, ln_g, ln_b);

    // weight prep
    float *w1h, *w1l;
    uint32_t *ew1p, *ew2p;
    cudaGetSymbolAddress((void**)&w1h,  g_w1h);
    cudaGetSymbolAddress((void**)&w1l,  g_w1l);
    cudaGetSymbolAddress((void**)&ew1p, g_ew1p);
    cudaGetSymbolAddress((void**)&ew2p, g_ew2p);
    split_copy<<<(DIM * HHALF / 4) / 256, 256>>>(r_w1, w1h, w1l);
    packw<<<(int)(((size_t)NEXP * (DIM / 2) * (HID / 4)) / 256), 256>>>(e_w1, ew1p, HID);
    packw<<<(int)(((size_t)NEXP * (HID / 2) * (DIM / 4)) / 256), 256>>>(e_w2, ew2p, DIM);

    // router path (split-tf32, exact-grade logits)
    gemm_router<<<dim3(HHALF / BN, N_TOK / BM), 256, SMEM_R>>>(w1h, w1l, r_b1);
    router_kernel<<<N_TOK / 8, 256>>>(r_w2, r_b2);
    scan_kernel<<<1, 32>>>();
    place_kernel<<<N_TOK / 256, 256>>>();

    // expert path (fp16 tensor cores)
    moe_mma16<1><<<dim3(HID / BN, N_TOK / BM, NEXP), 256, SMEM_H>>>(ew1p, e_b1);
    moe_mma16<2><<<dim3(DIM / BN, N_TOK / BM, NEXP), 256, SMEM_H>>>(ew2p, e_b2);

    // out = x + g1*y1 + g2*y2
    combine_kernel<<<N_TOK, 256>>>(x, out);
}

// round 12
// speedup vs baseline: 2.1184x; 1.2097x over previous
#include <cuda_runtime.h>
#include <cuda_fp16.h>
#include <cstdint>

// Problem constants
#define N_TOK 16384
#define DIM   1024
#define HID   4096
#define HHALF 2048
#define NEXP  8
#define EPSLN 1e-5f

// CTA tile
#define BM 128
#define BN 256
#define BSTRD 264

// ---------------- scratch -------------------------------------------------------
__device__ __half   g_xnh[(size_t)N_TOK * DIM];          // fp16 xn hi
__device__ __half   g_xnl[(size_t)N_TOK * DIM];          // fp16 xn lo residual
__device__ float    g_hr [(size_t)N_TOK * HHALF];
__device__ uint32_t g_hh [(size_t)(2 * N_TOK) * (HID / 2)];  // fp16 h, half2-packed
__device__ float    g_y  [(size_t)(2 * N_TOK) * DIM];
__device__ uint32_t g_w1hp[(size_t)(DIM / 2) * HHALF];   // w1 hi fp16 packed [k/2][n]
__device__ uint32_t g_w1lp[(size_t)(DIM / 2) * HHALF];   // w1 lo fp16 packed
__device__ uint32_t g_ew1p[(size_t)NEXP * (DIM / 2) * HID];
__device__ uint32_t g_ew2p[(size_t)NEXP * (HID / 2) * DIM];
__device__ int   g_cnt[NEXP];
__device__ int   g_off[NEXP];
__device__ int   g_fill[NEXP];
__device__ int   g_e12[N_TOK];
__device__ float g_g1[N_TOK];
__device__ float g_g2[N_TOK];
__device__ int   g_list[2 * N_TOK];
__device__ int   g_s1[N_TOK];
__device__ int   g_s2[N_TOK];

// ---------------- helpers -------------------------------------------------------
__device__ __forceinline__ uint32_t smem_u32(const void* p) {
    uint32_t a;
    asm("{ .reg .u64 t; cvta.to.shared.u64 t, %1; cvt.u32.u64 %0, t; }" : "=r"(a) : "l"(p));
    return a;
}
#define CP16(dst, src) \
    asm volatile("cp.async.cg.shared.global [%0], [%1], 16;" :: "r"(dst), "l"(src) : "memory")
#define CP_COMMIT() asm volatile("cp.async.commit_group;" ::: "memory")
#define CP_WAIT1()  asm volatile("cp.async.wait_group 1;" ::: "memory")
#define CP_WAIT0()  asm volatile("cp.async.wait_group 0;" ::: "memory")

__device__ __forceinline__ void mma16(float c[4], const uint32_t a[4], const uint32_t b[2]) {
    asm volatile(
        "mma.sync.aligned.m16n8k16.row.col.f32.f16.f16.f32 "
        "{%0,%1,%2,%3}, {%4,%5,%6,%7}, {%8,%9}, {%0,%1,%2,%3};"
        : "+f"(c[0]), "+f"(c[1]), "+f"(c[2]), "+f"(c[3])
        : "r"(a[0]), "r"(a[1]), "r"(a[2]), "r"(a[3]), "r"(b[0]), "r"(b[1]));
}

// ---------------- LayerNorm: fp16 hi + fp16 lo residual --------------------------
__global__ void ln_kernel(const float* __restrict__ x,
                          const float* __restrict__ gam,
                          const float* __restrict__ bet) {
    int row = blockIdx.x;
    const float* xr = x + (size_t)row * DIM;
    float s = 0.f, ss = 0.f;
    for (int i = threadIdx.x; i < DIM; i += 256) {
        float v = xr[i];
        s += v; ss += v * v;
    }
    __shared__ float sh[64];
    for (int o = 16; o; o >>= 1) {
        s  += __shfl_xor_sync(0xFFFFFFFFu, s,  o);
        ss += __shfl_xor_sync(0xFFFFFFFFu, ss, o);
    }
    int w = threadIdx.x >> 5, l = threadIdx.x & 31;
    if (l == 0) { sh[w] = s; sh[w + 32] = ss; }
    __syncthreads();
    if (w == 0) {
        s  = (l < 8) ? sh[l] : 0.f;
        ss = (l < 8) ? sh[l + 32] : 0.f;
        for (int o = 4; o; o >>= 1) {
            s  += __shfl_xor_sync(0xFFFFFFFFu, s,  o);
            ss += __shfl_xor_sync(0xFFFFFFFFu, ss, o);
        }
        if (l == 0) { sh[0] = s; sh[1] = ss; }
    }
    __syncthreads();
    float mu  = sh[0] * (1.0f / DIM);
    float var = sh[1] * (1.0f / DIM) - mu * mu;
    float r   = rsqrtf(var + EPSLN);
    for (int i = threadIdx.x; i < DIM; i += 256) {
        float v = (xr[i] - mu) * r * gam[i] + bet[i];
        __half h = __float2half_rn(v);
        g_xnh[(size_t)row * DIM + i] = h;
        g_xnl[(size_t)row * DIM + i] = __float2half_rn(v - __half2float(h));
    }
}

// ---------------- weight prep ----------------------------------------------------
// pack fp32 [R][N] -> fp16 half2 [R/2][N] u32 (low = even row)
__global__ void packw(const float* __restrict__ in, uint32_t* __restrict__ out,
                      int ncols) {
    size_t idx = (size_t)blockIdx.x * 256 + threadIdx.x;
    size_t n4 = (size_t)ncols / 4;
    size_t r2 = idx / n4;
    size_t c  = (idx % n4) * 4;
    const float4 v0 = *(const float4*)(in + (2 * r2) * ncols + c);
    const float4 v1 = *(const float4*)(in + (2 * r2 + 1) * ncols + c);
    uint4 o;
    __half2 t;
    t = __floats2half2_rn(v0.x, v1.x); o.x = *(uint32_t*)&t;
    t = __floats2half2_rn(v0.y, v1.y); o.y = *(uint32_t*)&t;
    t = __floats2half2_rn(v0.z, v1.z); o.z = *(uint32_t*)&t;
    t = __floats2half2_rn(v0.w, v1.w); o.w = *(uint32_t*)&t;
    *(uint4*)(out + r2 * ncols + c) = o;
}

// pack-split fp32 [R][N] -> hi/lo fp16 half2 [R/2][N]
__global__ void packw_split(const float* __restrict__ in,
                            uint32_t* __restrict__ hi, uint32_t* __restrict__ lo,
                            int ncols) {
    size_t idx = (size_t)blockIdx.x * 256 + threadIdx.x;
    size_t n4 = (size_t)ncols / 4;
    size_t r2 = idx / n4;
    size_t c  = (idx % n4) * 4;
    const float4 v0 = *(const float4*)(in + (2 * r2) * ncols + c);
    const float4 v1 = *(const float4*)(in + (2 * r2 + 1) * ncols + c);
    float e0[4] = {v0.x, v0.y, v0.z, v0.w};
    float e1[4] = {v1.x, v1.y, v1.z, v1.w};
    uint4 oh, ol;
    uint32_t* ohp = (uint32_t*)&oh;
    uint32_t* olp = (uint32_t*)&ol;
#pragma unroll
    for (int j = 0; j < 4; j++) {
        __half h0 = __float2half_rn(e0[j]);
        __half h1 = __float2half_rn(e1[j]);
        __half l0 = __float2half_rn(e0[j] - __half2float(h0));
        __half l1 = __float2half_rn(e1[j] - __half2float(h1));
        __half2 th = __halves2half2(h0, h1);
        __half2 tl = __halves2half2(l0, l1);
        ohp[j] = *(uint32_t*)&th;
        olp[j] = *(uint32_t*)&tl;
    }
    *(uint4*)(hi + r2 * ncols + c) = oh;
    *(uint4*)(lo + r2 * ncols + c) = ol;
}

// ---------------- Router logits + softmax top-2 + gates --------------------------
__global__ void router_kernel(const float* __restrict__ w2,
                              const float* __restrict__ b2) {
    int warp = threadIdx.x >> 5, lane = threadIdx.x & 31;
    int t = blockIdx.x * 8 + warp;
    const float* hrow = g_hr + (size_t)t * HHALF;
    float acc[NEXP] = {};
    for (int i = lane; i < HHALF; i += 32) {
        float v = hrow[i];
        const float4* wp = (const float4*)(w2 + i * NEXP);
        float4 w0 = __ldg(wp), w1 = __ldg(wp + 1);
        acc[0] += v * w0.x; acc[1] += v * w0.y; acc[2] += v * w0.z; acc[3] += v * w0.w;
        acc[4] += v * w1.x; acc[5] += v * w1.y; acc[6] += v * w1.z; acc[7] += v * w1.w;
    }
    for (int o = 16; o; o >>= 1)
#pragma unroll
        for (int e = 0; e < NEXP; e++)
            acc[e] += __shfl_xor_sync(0xFFFFFFFFu, acc[e], o);
    if (lane == 0) {
        float l[NEXP];
#pragma unroll
        for (int e = 0; e < NEXP; e++) l[e] = acc[e] + b2[e];
        int e1 = 0;
        for (int e = 1; e < NEXP; e++) if (l[e] > l[e1]) e1 = e;
        int e2 = -1;
        for (int e = 0; e < NEXP; e++) {
            if (e == e1) continue;
            if (e2 < 0 || l[e] > l[e2]) e2 = e;
        }
        float ed  = expf(l[e2] - l[e1]);
        float inv = 1.f / (1.f + ed);
        g_e12[t] = e1 | (e2 << 8);
        g_g1[t] = inv;
        g_g2[t] = ed * inv;
        atomicAdd(&g_cnt[e1], 1);
        atomicAdd(&g_cnt[e2], 1);
    }
}

__global__ void zero_cnt_kernel() {
    if (threadIdx.x < NEXP) g_cnt[threadIdx.x] = 0;
}
__global__ void scan_kernel() {
    if (threadIdx.x == 0) {
        int s = 0;
        for (int e = 0; e < NEXP; e++) { g_off[e] = s; s += g_cnt[e]; g_fill[e] = 0; }
    }
}
__global__ void place_kernel() {
    int t = blockIdx.x * 256 + threadIdx.x;
    if (t >= N_TOK) return;
    int e12 = g_e12[t];
    int e1 = e12 & 0xFF, e2 = e12 >> 8;
    int s1 = g_off[e1] + atomicAdd(&g_fill[e1], 1);
    g_list[s1] = t; g_s1[t] = s1;
    int s2 = g_off[e2] + atomicAdd(&g_fill[e2], 1);
    g_list[s2] = t; g_s2[t] = s2;
}

// ---------------- final combine --------------------------------------------------
__global__ void combine_kernel(const float* __restrict__ x, float* __restrict__ out) {
    int t = blockIdx.x;
    int s1 = g_s1[t], s2 = g_s2[t];
    float a = g_g1[t], b = g_g2[t];
    const float4* xr = (const float4*)(x   + (size_t)t  * DIM);
    const float4* y1 = (const float4*)(g_y + (size_t)s1 * DIM);
    const float4* y2 = (const float4*)(g_y + (size_t)s2 * DIM);
    float4* o = (float4*)(out + (size_t)t * DIM);
    int i = threadIdx.x;
    float4 xv = xr[i], v1 = y1[i], v2 = y2[i];
    float4 r;
    r.x = xv.x + a * v1.x + b * v2.x;
    r.y = xv.y + a * v1.y + b * v2.y;
    r.z = xv.z + a * v1.z + b * v2.z;
    r.w = xv.w + a * v1.w + b * v2.w;
    o[i] = r;
}

// ---------------- Router GEMM: split-fp16, 3 passes (hh, hl, lh) -----------------
// g_hr = relu((xh+xl) @ (wh+wl) + b1), M=16384 N=2048 K=1024. BKC=32 fp16.
__global__ void __launch_bounds__(256, 1)
gemm_router16(const uint32_t* __restrict__ Wh, const uint32_t* __restrict__ Wl,
              const float* __restrict__ bias) {
    constexpr int BKC  = 32;            // fp16 elems per chunk
    constexpr int KU   = BKC / 2;       // 16 u32
    constexpr int NC   = DIM / BKC;     // 32 chunks
    constexpr int AST  = KU + 4;        // 20 u32
    constexpr int ASZ  = BM * AST;      // 2560 u32
    constexpr int BST2 = BN + 8;        // 264 u32
    constexpr int BSZ  = KU * BST2;     // 4224 u32
    constexpr int STG  = 2 * (ASZ + BSZ);

    int bm = blockIdx.y * BM, bn = blockIdx.x * BN;
    extern __shared__ uint32_t smu[];
    uint32_t smb = smem_u32(smu);
    int tid = threadIdx.x, lane = tid & 31, wid = tid >> 5;
    int wm = (wid >> 2) * 64, wn = (wid & 3) * 64;

    // A: 128 rows x 16 u32 -> 2 CP16/thread per buffer
    const uint32_t* ah[2];
    const uint32_t* al[2];
    uint32_t adst[2];
#pragma unroll
    for (int j = 0; j < 2; j++) {
        int id = tid + 256 * j;
        int row = id >> 2, c4 = id & 3;
        adst[j] = (uint32_t)row * (AST * 4) + c4 * 16;
        int r = bm + row;
        ah[j] = (const uint32_t*)g_xnh + (size_t)r * (DIM / 2) + c4 * 4;
        al[j] = (const uint32_t*)g_xnl + (size_t)r * (DIM / 2) + c4 * 4;
    }
    // B: 16 k2-rows x 256 u32 -> 4 CP16/thread per buffer
    const uint32_t* bh[4];
    const uint32_t* bl[4];
    uint32_t bdst[4];
#pragma unroll
    for (int j = 0; j < 4; j++) {
        int id = tid + 256 * j;
        int kr = id >> 6, c = id & 63;
        bdst[j] = (uint32_t)kr * (BST2 * 4) + c * 16;
        bh[j] = Wh + (size_t)kr * HHALF + bn + c * 4;
        bl[j] = Wl + (size_t)kr * HHALF + bn + c * 4;
    }

    auto load = [&](int i, int st) {
        uint32_t s0 = smb + (uint32_t)st * STG * 4;
        uint32_t b0 = s0 + 2u * ASZ * 4;
        int ko = i * KU;
        size_t bko = (size_t)(i * KU) * HHALF;
#pragma unroll
        for (int j = 0; j < 2; j++) {
            CP16(s0 + adst[j], ah[j] + ko);
            CP16(s0 + ASZ * 4 + adst[j], al[j] + ko);
        }
#pragma unroll
        for (int j = 0; j < 4; j++) {
            CP16(b0 + bdst[j], bh[j] + bko);
            CP16(b0 + BSZ * 4 + bdst[j], bl[j] + bko);
        }
        CP_COMMIT();
    };

    float c[4][8][4] = {};
    load(0, 0);
    load(1, 1);

    int lr = lane >> 2, lc = lane & 3;
    for (int i = 0; i < NC; i++) {
        int st = i % 3;
        if (i + 2 < NC) { CP_WAIT1(); } else { CP_WAIT0(); }
        __syncthreads();
        if (i + 2 < NC) load(i + 2, (i + 2) % 3);

        const uint32_t* Au = smu + st * STG;
        const uint32_t* Al = Au + ASZ;
        const uint32_t* Bu = Au + 2 * ASZ;
        const uint32_t* Bl = Bu + BSZ;
#pragma unroll
        for (int ks = 0; ks < 2; ks++) {
            uint32_t a[4][4], a2[4][4], b[8][2], b2[8][2];
#pragma unroll
            for (int mt = 0; mt < 4; mt++) {
                const uint32_t* ap = Au + (wm + mt * 16 + lr) * AST + ks * 8 + lc;
                a[mt][0] = ap[0];
                a[mt][1] = ap[8 * AST];
                a[mt][2] = ap[4];
                a[mt][3] = ap[8 * AST + 4];
                const uint32_t* ap2 = Al + (wm + mt * 16 + lr) * AST + ks * 8 + lc;
                a2[mt][0] = ap2[0];
                a2[mt][1] = ap2[8 * AST];
                a2[mt][2] = ap2[4];
                a2[mt][3] = ap2[8 * AST + 4];
            }
#pragma unroll
            for (int nt = 0; nt < 8; nt++) {
                const uint32_t* bpp = Bu + (ks * 8 + lc) * BST2 + wn + nt * 8 + lr;
                b[nt][0] = bpp[0];
                b[nt][1] = bpp[4 * BST2];
                const uint32_t* bpp2 = Bl + (ks * 8 + lc) * BST2 + wn + nt * 8 + lr;
                b2[nt][0] = bpp2[0];
                b2[nt][1] = bpp2[4 * BST2];
            }
#pragma unroll
            for (int mt = 0; mt < 4; mt++)
#pragma unroll
                for (int nt = 0; nt < 8; nt++) {
                    mma16(c[mt][nt], a[mt],  b[nt]);    // hi*hi
                    mma16(c[mt][nt], a[mt],  b2[nt]);   // hi*lo
                    mma16(c[mt][nt], a2[mt], b[nt]);    // lo*hi
                }
        }
    }

#pragma unroll
    for (int mt = 0; mt < 4; mt++) {
#pragma unroll
        for (int half = 0; half < 2; half++) {
            int r = bm + wm + mt * 16 + lr + half * 8;
            float* row = g_hr + (size_t)r * HHALF;
#pragma unroll
            for (int nt = 0; nt < 8; nt++) {
                int col = bn + wn + nt * 8 + lc * 2;
                float v0 = c[mt][nt][half * 2]     + bias[col];
                float v1 = c[mt][nt][half * 2 + 1] + bias[col + 1];
                float2 st2;
                st2.x = fmaxf(v0, 0.f); st2.y = fmaxf(v1, 0.f);
                *(float2*)(row + col) = st2;
            }
        }
    }
}

// ---------------- Expert GEMMs: fp16 m16n8k16, BKC=64, 3-stage -------------------
template <int MODE>
__global__ void __launch_bounds__(256, 1)
moe_mma16(const uint32_t* __restrict__ Wp, const float* __restrict__ bias) {
    constexpr int Kd   = (MODE == 2) ? HID : DIM;
    constexpr int Nd   = (MODE == 1) ? HID : DIM;
    constexpr int BKC  = 64;
    constexpr int KU   = BKC / 2;
    constexpr int NC   = Kd / BKC;
    constexpr int AST  = KU + 4;
    constexpr int ASZ  = BM * AST;
    constexpr int BST2 = BN + 8;
    constexpr int BSZ  = KU * BST2;
    constexpr int STG  = ASZ + BSZ;

    int bm = blockIdx.y * BM, bn = blockIdx.x * BN;
    int e = blockIdx.z;
    int cnt = g_cnt[e];
    if (bm >= cnt) return;
    int base = g_off[e];
    const uint32_t* W = Wp + (size_t)e * (Kd / 2) * Nd;
    const float* bp = bias + e * Nd;

    extern __shared__ uint32_t smu[];
    uint32_t smb = smem_u32(smu);
    int tid = threadIdx.x, lane = tid & 31, wid = tid >> 5;
    int wm = (wid >> 2) * 64, wn = (wid & 3) * 64;

    const uint32_t* ah[4];
    uint32_t adst[4];
#pragma unroll
    for (int j = 0; j < 4; j++) {
        int id = tid + 256 * j;
        int row = id >> 3, c4 = id & 7;
        adst[j] = (uint32_t)row * (AST * 4) + c4 * 16;
        int r = bm + row; if (r >= cnt) r = cnt - 1;
        if (MODE == 1) {
            int tok = g_list[base + r];
            ah[j] = (const uint32_t*)g_xnh + (size_t)tok * (DIM / 2) + c4 * 4;
        } else {
            ah[j] = g_hh + (size_t)(base + r) * (HID / 2) + c4 * 4;
        }
    }
    const uint32_t* bh[8];
    uint32_t bdst[8];
#pragma unroll
    for (int j = 0; j < 8; j++) {
        int id = tid + 256 * j;
        int kr = id >> 6, c = id & 63;
        bdst[j] = (uint32_t)kr * (BST2 * 4) + c * 16;
        bh[j] = W + (size_t)kr * Nd + bn + c * 4;
    }

    auto load = [&](int i, int st) {
        uint32_t s0 = smb + (uint32_t)st * STG * 4;
        uint32_t b0 = s0 + ASZ * 4;
        int ko = i * KU;
        size_t bko = (size_t)(i * KU) * Nd;
#pragma unroll
        for (int j = 0; j < 4; j++) CP16(s0 + adst[j], ah[j] + ko);
#pragma unroll
        for (int j = 0; j < 8; j++) CP16(b0 + bdst[j], bh[j] + bko);
        CP_COMMIT();
    };

    float c[4][8][4] = {};
    load(0, 0);
    load(1, 1);

    int lr = lane >> 2, lc = lane & 3;
    for (int i = 0; i < NC; i++) {
        int st = i % 3;
        if (i + 2 < NC) { CP_WAIT1(); } else { CP_WAIT0(); }
        __syncthreads();
        if (i + 2 < NC) load(i + 2, (i + 2) % 3);

        const uint32_t* Au = smu + st * STG;
        const uint32_t* Bu = Au + ASZ;
#pragma unroll
        for (int ks = 0; ks < 4; ks++) {
            uint32_t a[4][4], b[8][2];
#pragma unroll
            for (int mt = 0; mt < 4; mt++) {
                const uint32_t* ap = Au + (wm + mt * 16 + lr) * AST + ks * 8 + lc;
                a[mt][0] = ap[0];
                a[mt][1] = ap[8 * AST];
                a[mt][2] = ap[4];
                a[mt][3] = ap[8 * AST + 4];
            }
#pragma unroll
            for (int nt = 0; nt < 8; nt++) {
                const uint32_t* bpp = Bu + (ks * 8 + lc) * BST2 + wn + nt * 8 + lr;
                b[nt][0] = bpp[0];
                b[nt][1] = bpp[4 * BST2];
            }
#pragma unroll
            for (int mt = 0; mt < 4; mt++)
#pragma unroll
                for (int nt = 0; nt < 8; nt++)
                    mma16(c[mt][nt], a[mt], b[nt]);
        }
    }

#pragma unroll
    for (int mt = 0; mt < 4; mt++) {
#pragma unroll
        for (int half = 0; half < 2; half++) {
            int r = bm + wm + mt * 16 + lr + half * 8;
            if (r >= cnt) continue;
            if (MODE == 1) {
                uint32_t* row = g_hh + (size_t)(base + r) * (HID / 2);
#pragma unroll
                for (int nt = 0; nt < 8; nt++) {
                    int col = bn + wn + nt * 8 + lc * 2;
                    float v0 = fmaxf(c[mt][nt][half * 2]     + bp[col],     0.f);
                    float v1 = fmaxf(c[mt][nt][half * 2 + 1] + bp[col + 1], 0.f);
                    __half2 hv = __floats2half2_rn(v0, v1);
                    row[col / 2] = *(uint32_t*)&hv;
                }
            } else {
                float* row = g_y + (size_t)(base + r) * DIM;
#pragma unroll
                for (int nt = 0; nt < 8; nt++) {
                    int col = bn + wn + nt * 8 + lc * 2;
                    float2 st2;
                    st2.x = c[mt][nt][half * 2]     + bp[col];
                    st2.y = c[mt][nt][half * 2 + 1] + bp[col + 1];
                    *(float2*)(row + col) = st2;
                }
            }
        }
    }
}

// ---------------- launch ---------------------------------------------------------
extern "C" void kernel_launch(void* const* d_in, const int* in_sizes, int n_in,
                              void* d_out, int out_size) {
    const float* x    = (const float*)d_in[0];
    const float* ln_g = (const float*)d_in[1];
    const float* ln_b = (const float*)d_in[2];
    const float* r_w1 = (const float*)d_in[3];
    const float* r_b1 = (const float*)d_in[4];
    const float* r_w2 = (const float*)d_in[5];
    const float* r_b2 = (const float*)d_in[6];
    const float* e_w1 = (const float*)d_in[7];
    const float* e_b1 = (const float*)d_in[8];
    const float* e_w2 = (const float*)d_in[9];
    const float* e_b2 = (const float*)d_in[10];
    float* out = (float*)d_out;

    // smem: router split-fp16 3x2x(2560+4224)x4 = 162816 ; fp16 GEMM 156672
    const int SMEM_R = 3 * 2 * (BM * 20 + 16 * 264) * 4;
    const int SMEM_H = 3 * (BM * 36 + 32 * 264) * 4;

    static int configured = 0;
    if (!configured) {
        cudaFuncSetAttribute(gemm_router16, cudaFuncAttributeMaxDynamicSharedMemorySize, SMEM_R);
        cudaFuncSetAttribute(moe_mma16<1>, cudaFuncAttributeMaxDynamicSharedMemorySize, SMEM_H);
        cudaFuncSetAttribute(moe_mma16<2>, cudaFuncAttributeMaxDynamicSharedMemorySize, SMEM_H);
        configured = 1;
    }

    zero_cnt_kernel<<<1, 32>>>();
    ln_kernel<<<N_TOK, 256>>>(x, ln_g, ln_b);

    // weight prep
    uint32_t *w1hp, *w1lp, *ew1p, *ew2p;
    cudaGetSymbolAddress((void**)&w1hp, g_w1hp);
    cudaGetSymbolAddress((void**)&w1lp, g_w1lp);
    cudaGetSymbolAddress((void**)&ew1p, g_ew1p);
    cudaGetSymbolAddress((void**)&ew2p, g_ew2p);
    packw_split<<<(int)(((size_t)(DIM / 2) * (HHALF / 4)) / 256), 256>>>(r_w1, w1hp, w1lp, HHALF);
    packw<<<(int)(((size_t)NEXP * (DIM / 2) * (HID / 4)) / 256), 256>>>(e_w1, ew1p, HID);
    packw<<<(int)(((size_t)NEXP * (HID / 2) * (DIM / 4)) / 256), 256>>>(e_w2, ew2p, DIM);

    // router path (split-fp16, exact-grade logits)
    gemm_router16<<<dim3(HHALF / BN, N_TOK / BM), 256, SMEM_R>>>(w1hp, w1lp, r_b1);
    router_kernel<<<N_TOK / 8, 256>>>(r_w2, r_b2);
    scan_kernel<<<1, 32>>>();
    place_kernel<<<N_TOK / 256, 256>>>();

    // expert path (fp16 tensor cores)
    moe_mma16<1><<<dim3(HID / BN, N_TOK / BM, NEXP), 256, SMEM_H>>>(ew1p, e_b1);
    moe_mma16<2><<<dim3(DIM / BN, N_TOK / BM, NEXP), 256, SMEM_H>>>(ew2p, e_b2);

    // out = x + g1*y1 + g2*y2
    combine_kernel<<<N_TOK, 256>>>(x, out);
}

// round 14
// speedup vs baseline: 2.1538x; 1.0167x over previous
#include <cuda_runtime.h>
#include <cuda_fp16.h>
#include <cstdint>

// Problem constants
#define N_TOK 16384
#define DIM   1024
#define HID   4096
#define HHALF 2048
#define NEXP  8
#define EPSLN 1e-5f

// CTA tile
#define BM 128
#define BN 256
#define B_ROWB 2080    // B smem row stride bytes (256 u64 + 32B pad): conflict-free LDS.64
#define B_ROWU 260     // same in u64

// ---------------- scratch -------------------------------------------------------
__device__ __half    g_xnh[(size_t)N_TOK * DIM];
__device__ __half    g_xnl[(size_t)N_TOK * DIM];
__device__ float     g_hr [(size_t)N_TOK * HHALF];
__device__ uint32_t  g_hh [(size_t)(2 * N_TOK) * (HID / 2)];
__device__ float     g_y  [(size_t)(2 * N_TOK) * DIM];
__device__ uint64_t  g_w1hp[(size_t)(DIM / 4) * HHALF];   // u64-interleaved fp16 hi
__device__ uint64_t  g_w1lp[(size_t)(DIM / 4) * HHALF];   // u64-interleaved fp16 lo
__device__ uint64_t  g_ew1p[(size_t)NEXP * (DIM / 4) * HID];
__device__ uint64_t  g_ew2p[(size_t)NEXP * (HID / 4) * DIM];
__device__ int   g_cnt[NEXP];
__device__ int   g_off[NEXP];
__device__ int   g_fill[NEXP];
__device__ int   g_e12[N_TOK];
__device__ float g_g1[N_TOK];
__device__ float g_g2[N_TOK];
__device__ int   g_list[2 * N_TOK];
__device__ int   g_s1[N_TOK];
__device__ int   g_s2[N_TOK];

// ---------------- helpers -------------------------------------------------------
__device__ __forceinline__ uint32_t smem_u32(const void* p) {
    uint32_t a;
    asm("{ .reg .u64 t; cvta.to.shared.u64 t, %1; cvt.u32.u64 %0, t; }" : "=r"(a) : "l"(p));
    return a;
}
#define CP16(dst, src) \
    asm volatile("cp.async.cg.shared.global [%0], [%1], 16;" :: "r"(dst), "l"(src) : "memory")
#define CP_COMMIT() asm volatile("cp.async.commit_group;" ::: "memory")
#define CP_WAIT1()  asm volatile("cp.async.wait_group 1;" ::: "memory")
#define CP_WAIT0()  asm volatile("cp.async.wait_group 0;" ::: "memory")

#define LDSM4(r0, r1, r2, r3, addr) \
    asm volatile("ldmatrix.sync.aligned.m8n8.x4.shared.b16 {%0,%1,%2,%3}, [%4];" \
                 : "=r"(r0), "=r"(r1), "=r"(r2), "=r"(r3) : "r"(addr))

__device__ __forceinline__ void mma16(float c[4], const uint32_t a[4], const uint32_t b[2]) {
    asm volatile(
        "mma.sync.aligned.m16n8k16.row.col.f32.f16.f16.f32 "
        "{%0,%1,%2,%3}, {%4,%5,%6,%7}, {%8,%9}, {%0,%1,%2,%3};"
        : "+f"(c[0]), "+f"(c[1]), "+f"(c[2]), "+f"(c[3])
        : "r"(a[0]), "r"(a[1]), "r"(a[2]), "r"(a[3]), "r"(b[0]), "r"(b[1]));
}

// ---------------- LayerNorm: fp16 hi + fp16 lo residual --------------------------
__global__ void ln_kernel(const float* __restrict__ x,
                          const float* __restrict__ gam,
                          const float* __restrict__ bet) {
    int row = blockIdx.x;
    const float* xr = x + (size_t)row * DIM;
    float s = 0.f, ss = 0.f;
    for (int i = threadIdx.x; i < DIM; i += 256) {
        float v = xr[i];
        s += v; ss += v * v;
    }
    __shared__ float sh[64];
    for (int o = 16; o; o >>= 1) {
        s  += __shfl_xor_sync(0xFFFFFFFFu, s,  o);
        ss += __shfl_xor_sync(0xFFFFFFFFu, ss, o);
    }
    int w = threadIdx.x >> 5, l = threadIdx.x & 31;
    if (l == 0) { sh[w] = s; sh[w + 32] = ss; }
    __syncthreads();
    if (w == 0) {
        s  = (l < 8) ? sh[l] : 0.f;
        ss = (l < 8) ? sh[l + 32] : 0.f;
        for (int o = 4; o; o >>= 1) {
            s  += __shfl_xor_sync(0xFFFFFFFFu, s,  o);
            ss += __shfl_xor_sync(0xFFFFFFFFu, ss, o);
        }
        if (l == 0) { sh[0] = s; sh[1] = ss; }
    }
    __syncthreads();
    float mu  = sh[0] * (1.0f / DIM);
    float var = sh[1] * (1.0f / DIM) - mu * mu;
    float r   = rsqrtf(var + EPSLN);
    for (int i = threadIdx.x; i < DIM; i += 256) {
        float v = (xr[i] - mu) * r * gam[i] + bet[i];
        __half h = __float2half_rn(v);
        g_xnh[(size_t)row * DIM + i] = h;
        g_xnl[(size_t)row * DIM + i] = __float2half_rn(v - __half2float(h));
    }
}

// ---------------- weight prep: u64-interleaved fp16 pack -------------------------
// out u64[(ko*4+lc)*N + n] = { half2(w[16ko+2lc][n],   w[16ko+2lc+1][n]),
//                              half2(w[16ko+2lc+8][n], w[16ko+2lc+9][n]) }
__global__ void packw2(const float* __restrict__ in, uint64_t* __restrict__ out,
                       int N) {
    size_t idx = (size_t)blockIdx.x * 256 + threadIdx.x;   // one uint4 (2 u64, 2 n)
    size_t nh = (size_t)N / 2;
    size_t rowp = idx / nh;
    size_t n = (idx % nh) * 2;
    size_t ko = rowp >> 2, lc = rowp & 3;
    size_t k0 = ko * 16 + lc * 2;
    const float* w0 = in + k0 * N + n;
    float a0 = w0[0],         a0b = w0[1];
    float a1 = w0[N],         a1b = w0[N + 1];
    float a8 = w0[8 * N],     a8b = w0[8 * N + 1];
    float a9 = w0[9 * N],     a9b = w0[9 * N + 1];
    __half2 h0 = __floats2half2_rn(a0, a1);
    __half2 h1 = __floats2half2_rn(a8, a9);
    __half2 h2 = __floats2half2_rn(a0b, a1b);
    __half2 h3 = __floats2half2_rn(a8b, a9b);
    uint4 o;
    o.x = *(uint32_t*)&h0; o.y = *(uint32_t*)&h1;
    o.z = *(uint32_t*)&h2; o.w = *(uint32_t*)&h3;
    *(uint4*)(out + rowp * N + n) = o;
}

// split variant: hi = rn(w), lo = rn(w - hi)
__global__ void packw2_split(const float* __restrict__ in,
                             uint64_t* __restrict__ hi, uint64_t* __restrict__ lo,
                             int N) {
    size_t idx = (size_t)blockIdx.x * 256 + threadIdx.x;
    size_t nh = (size_t)N / 2;
    size_t rowp = idx / nh;
    size_t n = (idx % nh) * 2;
    size_t ko = rowp >> 2, lc = rowp & 3;
    size_t k0 = ko * 16 + lc * 2;
    const float* w0 = in + k0 * N + n;
    float v[8] = { w0[0], w0[N], w0[8 * N], w0[9 * N],
                   w0[1], w0[N + 1], w0[8 * N + 1], w0[9 * N + 1] };
    __half hh[8];
    __half ll[8];
#pragma unroll
    for (int j = 0; j < 8; j++) {
        hh[j] = __float2half_rn(v[j]);
        ll[j] = __float2half_rn(v[j] - __half2float(hh[j]));
    }
    uint4 oh, ol;
    __half2 t;
    t = __halves2half2(hh[0], hh[1]); oh.x = *(uint32_t*)&t;
    t = __halves2half2(hh[2], hh[3]); oh.y = *(uint32_t*)&t;
    t = __halves2half2(hh[4], hh[5]); oh.z = *(uint32_t*)&t;
    t = __halves2half2(hh[6], hh[7]); oh.w = *(uint32_t*)&t;
    t = __halves2half2(ll[0], ll[1]); ol.x = *(uint32_t*)&t;
    t = __halves2half2(ll[2], ll[3]); ol.y = *(uint32_t*)&t;
    t = __halves2half2(ll[4], ll[5]); ol.z = *(uint32_t*)&t;
    t = __halves2half2(ll[6], ll[7]); ol.w = *(uint32_t*)&t;
    *(uint4*)(hi + rowp * N + n) = oh;
    *(uint4*)(lo + rowp * N + n) = ol;
}

// ---------------- Router logits + softmax top-2 + gates --------------------------
__global__ void router_kernel(const float* __restrict__ w2,
                              const float* __restrict__ b2) {
    int warp = threadIdx.x >> 5, lane = threadIdx.x & 31;
    int t = blockIdx.x * 8 + warp;
    const float* hrow = g_hr + (size_t)t * HHALF;
    float acc[NEXP] = {};
    for (int i = lane; i < HHALF; i += 32) {
        float v = hrow[i];
        const float4* wp = (const float4*)(w2 + i * NEXP);
        float4 w0 = __ldg(wp), w1 = __ldg(wp + 1);
        acc[0] += v * w0.x; acc[1] += v * w0.y; acc[2] += v * w0.z; acc[3] += v * w0.w;
        acc[4] += v * w1.x; acc[5] += v * w1.y; acc[6] += v * w1.z; acc[7] += v * w1.w;
    }
    for (int o = 16; o; o >>= 1)
#pragma unroll
        for (int e = 0; e < NEXP; e++)
            acc[e] += __shfl_xor_sync(0xFFFFFFFFu, acc[e], o);
    if (lane == 0) {
        float l[NEXP];
#pragma unroll
        for (int e = 0; e < NEXP; e++) l[e] = acc[e] + b2[e];
        int e1 = 0;
        for (int e = 1; e < NEXP; e++) if (l[e] > l[e1]) e1 = e;
        int e2 = -1;
        for (int e = 0; e < NEXP; e++) {
            if (e == e1) continue;
            if (e2 < 0 || l[e] > l[e2]) e2 = e;
        }
        float ed  = expf(l[e2] - l[e1]);
        float inv = 1.f / (1.f + ed);
        g_e12[t] = e1 | (e2 << 8);
        g_g1[t] = inv;
        g_g2[t] = ed * inv;
        atomicAdd(&g_cnt[e1], 1);
        atomicAdd(&g_cnt[e2], 1);
    }
}

__global__ void zero_cnt_kernel() {
    if (threadIdx.x < NEXP) g_cnt[threadIdx.x] = 0;
}
__global__ void scan_kernel() {
    if (threadIdx.x == 0) {
        int s = 0;
        for (int e = 0; e < NEXP; e++) { g_off[e] = s; s += g_cnt[e]; g_fill[e] = 0; }
    }
}
__global__ void place_kernel() {
    int t = blockIdx.x * 256 + threadIdx.x;
    if (t >= N_TOK) return;
    int e12 = g_e12[t];
    int e1 = e12 & 0xFF, e2 = e12 >> 8;
    int s1 = g_off[e1] + atomicAdd(&g_fill[e1], 1);
    g_list[s1] = t; g_s1[t] = s1;
    int s2 = g_off[e2] + atomicAdd(&g_fill[e2], 1);
    g_list[s2] = t; g_s2[t] = s2;
}

// ---------------- final combine --------------------------------------------------
__global__ void combine_kernel(const float* __restrict__ x, float* __restrict__ out) {
    int t = blockIdx.x;
    int s1 = g_s1[t], s2 = g_s2[t];
    float a = g_g1[t], b = g_g2[t];
    const float4* xr = (const float4*)(x   + (size_t)t  * DIM);
    const float4* y1 = (const float4*)(g_y + (size_t)s1 * DIM);
    const float4* y2 = (const float4*)(g_y + (size_t)s2 * DIM);
    float4* o = (float4*)(out + (size_t)t * DIM);
    int i = threadIdx.x;
    float4 xv = xr[i], v1 = y1[i], v2 = y2[i];
    float4 r;
    r.x = xv.x + a * v1.x + b * v2.x;
    r.y = xv.y + a * v1.y + b * v2.y;
    r.z = xv.z + a * v1.z + b * v2.z;
    r.w = xv.w + a * v1.w + b * v2.w;
    o[i] = r;
}

// ---------------- Router GEMM: split-fp16, ldmatrix + LDS.64 ---------------------
// g_hr = relu((xh+xl)@(wh+wl) + b1), M=16384 N=2048 K=1024. BKC=32 fp16.
__global__ void __launch_bounds__(256, 1)
gemm_router16(const uint64_t* __restrict__ Wh, const uint64_t* __restrict__ Wl,
              const float* __restrict__ bias) {
    constexpr int BKC  = 32;
    constexpr int NC   = DIM / BKC;
    constexpr int AST4 = 80;                 // A row stride bytes (16 u32 + 4 pad)
    constexpr int ASZ  = BM * AST4;          // 10240 B per buffer
    constexpr int BSZ  = 8 * B_ROWB;         // 16640 B per buffer (8 p-rows)
    constexpr int STG  = 2 * ASZ + 2 * BSZ;  // 53760 B

    int bm = blockIdx.y * BM, bn = blockIdx.x * BN;
    extern __shared__ char smc[];
    uint32_t smb = smem_u32(smc);
    int tid = threadIdx.x, lane = tid & 31, wid = tid >> 5;
    int wm = (wid >> 2) * 64, wn = (wid & 3) * 64;

    // A cp.async: per buffer 2 chunks/thread
    const uint32_t* ah[2];
    const uint32_t* al[2];
    uint32_t adst[2];
#pragma unroll
    for (int j = 0; j < 2; j++) {
        int id = tid + 256 * j;
        int row = id >> 2, c4 = id & 3;
        adst[j] = (uint32_t)row * AST4 + c4 * 16;
        ah[j] = (const uint32_t*)g_xnh + (size_t)(bm + row) * (DIM / 2) + c4 * 4;
        al[j] = (const uint32_t*)g_xnl + (size_t)(bm + row) * (DIM / 2) + c4 * 4;
    }
    // B cp.async: per buffer 4 chunks/thread (8 p-rows x 256 u64)
    const uint64_t* bh[4];
    const uint64_t* bl[4];
    uint32_t bdst[4];
#pragma unroll
    for (int j = 0; j < 4; j++) {
        int id = tid + 256 * j;
        int p = id >> 7, nn = (id & 127) * 2;
        bdst[j] = (uint32_t)p * B_ROWB + nn * 8;
        bh[j] = Wh + (size_t)p * HHALF + bn + nn;
        bl[j] = Wl + (size_t)p * HHALF + bn + nn;
    }

    auto load = [&](int i, int st) {
        uint32_t s0 = smb + (uint32_t)st * STG;
        int ko = i * 16;                     // u32 offset along k for A (32 halves)
        size_t bko = (size_t)i * 8 * HHALF;  // 8 u64 p-rows per chunk
#pragma unroll
        for (int j = 0; j < 2; j++) {
            CP16(s0 + adst[j], ah[j] + ko);
            CP16(s0 + ASZ + adst[j], al[j] + ko);
        }
#pragma unroll
        for (int j = 0; j < 4; j++) {
            CP16(s0 + 2 * ASZ + bdst[j], bh[j] + bko);
            CP16(s0 + 2 * ASZ + BSZ + bdst[j], bl[j] + bko);
        }
        CP_COMMIT();
    };

    float c[4][8][4] = {};
    load(0, 0);
    load(1, 1);

    int lr = lane >> 2, lc = lane & 3;
    uint32_t arow_off = (uint32_t)(wm + (lane & 15)) * AST4 + (lane >> 4) * 16;
    for (int i = 0; i < NC; i++) {
        int st = i % 3;
        if (i + 2 < NC) { CP_WAIT1(); } else { CP_WAIT0(); }
        __syncthreads();
        if (i + 2 < NC) load(i + 2, (i + 2) % 3);

        uint32_t sA  = smb + st * STG;
        uint32_t sA2 = sA + ASZ;
        const uint64_t* Bu = (const uint64_t*)(smc + st * STG + 2 * ASZ);
        const uint64_t* Bl2 = (const uint64_t*)(smc + st * STG + 2 * ASZ + BSZ);
#pragma unroll
        for (int ks = 0; ks < 2; ks++) {
            uint32_t a[4][4], a2[4][4], b[8][2], b2[8][2];
#pragma unroll
            for (int mt = 0; mt < 4; mt++) {
                LDSM4(a[mt][0], a[mt][1], a[mt][2], a[mt][3],
                      sA + arow_off + mt * 16 * AST4 + ks * 32);
                LDSM4(a2[mt][0], a2[mt][1], a2[mt][2], a2[mt][3],
                      sA2 + arow_off + mt * 16 * AST4 + ks * 32);
            }
            int prow = ks * 4 + lc;
#pragma unroll
            for (int nt = 0; nt < 8; nt++) {
                uint2 v  = *(const uint2*)(Bu  + (size_t)prow * B_ROWU + wn + nt * 8 + lr);
                uint2 v2 = *(const uint2*)(Bl2 + (size_t)prow * B_ROWU + wn + nt * 8 + lr);
                b[nt][0] = v.x;  b[nt][1] = v.y;
                b2[nt][0] = v2.x; b2[nt][1] = v2.y;
            }
#pragma unroll
            for (int mt = 0; mt < 4; mt++)
#pragma unroll
                for (int nt = 0; nt < 8; nt++) {
                    mma16(c[mt][nt], a[mt],  b[nt]);
                    mma16(c[mt][nt], a[mt],  b2[nt]);
                    mma16(c[mt][nt], a2[mt], b[nt]);
                }
        }
    }

#pragma unroll
    for (int mt = 0; mt < 4; mt++) {
#pragma unroll
        for (int half = 0; half < 2; half++) {
            int r = bm + wm + mt * 16 + lr + half * 8;
            float* row = g_hr + (size_t)r * HHALF;
#pragma unroll
            for (int nt = 0; nt < 8; nt++) {
                int col = bn + wn + nt * 8 + lc * 2;
                float v0 = c[mt][nt][half * 2]     + bias[col];
                float v1 = c[mt][nt][half * 2 + 1] + bias[col + 1];
                float2 st2;
                st2.x = fmaxf(v0, 0.f); st2.y = fmaxf(v1, 0.f);
                *(float2*)(row + col) = st2;
            }
        }
    }
}

// ---------------- Expert GEMMs: fp16, ldmatrix + LDS.64, BKC=64 ------------------
template <int MODE>
__global__ void __launch_bounds__(256, 1)
moe_mma16(const uint64_t* __restrict__ Wp, const float* __restrict__ bias) {
    constexpr int Kd   = (MODE == 2) ? HID : DIM;
    constexpr int Nd   = (MODE == 1) ? HID : DIM;
    constexpr int BKC  = 64;
    constexpr int NC   = Kd / BKC;
    constexpr int AST4 = 144;                // A row stride bytes (32 u32 + 4 pad)
    constexpr int ASZ  = BM * AST4;          // 18432
    constexpr int BSZ  = 16 * B_ROWB;        // 33280 (16 p-rows)
    constexpr int STG  = ASZ + BSZ;          // 51712

    int bm = blockIdx.y * BM, bn = blockIdx.x * BN;
    int e = blockIdx.z;
    int cnt = g_cnt[e];
    if (bm >= cnt) return;
    int base = g_off[e];
    const uint64_t* W = Wp + (size_t)e * (Kd / 4) * Nd;
    const float* bp = bias + e * Nd;

    extern __shared__ char smc[];
    uint32_t smb = smem_u32(smc);
    int tid = threadIdx.x, lane = tid & 31, wid = tid >> 5;
    int wm = (wid >> 2) * 64, wn = (wid & 3) * 64;

    const uint32_t* ah[4];
    uint32_t adst[4];
#pragma unroll
    for (int j = 0; j < 4; j++) {
        int id = tid + 256 * j;
        int row = id >> 3, c4 = id & 7;
        adst[j] = (uint32_t)row * AST4 + c4 * 16;
        int r = bm + row; if (r >= cnt) r = cnt - 1;
        if (MODE == 1) {
            int tok = g_list[base + r];
            ah[j] = (const uint32_t*)g_xnh + (size_t)tok * (DIM / 2) + c4 * 4;
        } else {
            ah[j] = g_hh + (size_t)(base + r) * (HID / 2) + c4 * 4;
        }
    }
    const uint64_t* bh[8];
    uint32_t bdst[8];
#pragma unroll
    for (int j = 0; j < 8; j++) {
        int id = tid + 256 * j;
        int p = id >> 7, nn = (id & 127) * 2;
        bdst[j] = (uint32_t)p * B_ROWB + nn * 8;
        bh[j] = W + (size_t)p * Nd + bn + nn;
    }

    auto load = [&](int i, int st) {
        uint32_t s0 = smb + (uint32_t)st * STG;
        int ko = i * 32;                     // u32 offset along k for A (64 halves)
        size_t bko = (size_t)i * 16 * Nd;    // 16 u64 p-rows per chunk
#pragma unroll
        for (int j = 0; j < 4; j++) CP16(s0 + adst[j], ah[j] + ko);
#pragma unroll
        for (int j = 0; j < 8; j++) CP16(s0 + ASZ + bdst[j], bh[j] + bko);
        CP_COMMIT();
    };

    float c[4][8][4] = {};
    load(0, 0);
    load(1, 1);

    int lr = lane >> 2, lc = lane & 3;
    uint32_t arow_off = (uint32_t)(wm + (lane & 15)) * AST4 + (lane >> 4) * 16;
    for (int i = 0; i < NC; i++) {
        int st = i % 3;
        if (i + 2 < NC) { CP_WAIT1(); } else { CP_WAIT0(); }
        __syncthreads();
        if (i + 2 < NC) load(i + 2, (i + 2) % 3);

        uint32_t sA = smb + st * STG;
        const uint64_t* Bu = (const uint64_t*)(smc + st * STG + ASZ);
#pragma unroll
        for (int ks = 0; ks < 4; ks++) {
            uint32_t a[4][4], b[8][2];
#pragma unroll
            for (int mt = 0; mt < 4; mt++)
                LDSM4(a[mt][0], a[mt][1], a[mt][2], a[mt][3],
                      sA + arow_off + mt * 16 * AST4 + ks * 32);
            int prow = ks * 4 + lc;
#pragma unroll
            for (int nt = 0; nt < 8; nt++) {
                uint2 v = *(const uint2*)(Bu + (size_t)prow * B_ROWU + wn + nt * 8 + lr);
                b[nt][0] = v.x; b[nt][1] = v.y;
            }
#pragma unroll
            for (int mt = 0; mt < 4; mt++)
#pragma unroll
                for (int nt = 0; nt < 8; nt++)
                    mma16(c[mt][nt], a[mt], b[nt]);
        }
    }

#pragma unroll
    for (int mt = 0; mt < 4; mt++) {
#pragma unroll
        for (int half = 0; half < 2; half++) {
            int r = bm + wm + mt * 16 + lr + half * 8;
            if (r >= cnt) continue;
            if (MODE == 1) {
                uint32_t* row = g_hh + (size_t)(base + r) * (HID / 2);
#pragma unroll
                for (int nt = 0; nt < 8; nt++) {
                    int col = bn + wn + nt * 8 + lc * 2;
                    float v0 = fmaxf(c[mt][nt][half * 2]     + bp[col],     0.f);
                    float v1 = fmaxf(c[mt][nt][half * 2 + 1] + bp[col + 1], 0.f);
                    __half2 hv = __floats2half2_rn(v0, v1);
                    row[col / 2] = *(uint32_t*)&hv;
                }
            } else {
                float* row = g_y + (size_t)(base + r) * DIM;
#pragma unroll
                for (int nt = 0; nt < 8; nt++) {
                    int col = bn + wn + nt * 8 + lc * 2;
                    float2 st2;
                    st2.x = c[mt][nt][half * 2]     + bp[col];
                    st2.y = c[mt][nt][half * 2 + 1] + bp[col + 1];
                    *(float2*)(row + col) = st2;
                }
            }
        }
    }
}

// ---------------- launch ---------------------------------------------------------
extern "C" void kernel_launch(void* const* d_in, const int* in_sizes, int n_in,
                              void* d_out, int out_size) {
    const float* x    = (const float*)d_in[0];
    const float* ln_g = (const float*)d_in[1];
    const float* ln_b = (const float*)d_in[2];
    const float* r_w1 = (const float*)d_in[3];
    const float* r_b1 = (const float*)d_in[4];
    const float* r_w2 = (const float*)d_in[5];
    const float* r_b2 = (const float*)d_in[6];
    const float* e_w1 = (const float*)d_in[7];
    const float* e_b1 = (const float*)d_in[8];
    const float* e_w2 = (const float*)d_in[9];
    const float* e_b2 = (const float*)d_in[10];
    float* out = (float*)d_out;

    const int SMEM_R = 3 * (2 * (BM * 80) + 2 * (8 * B_ROWB));    // 161280
    const int SMEM_H = 3 * (BM * 144 + 16 * B_ROWB);              // 155136

    static int configured = 0;
    if (!configured) {
        cudaFuncSetAttribute(gemm_router16, cudaFuncAttributeMaxDynamicSharedMemorySize, SMEM_R);
        cudaFuncSetAttribute(moe_mma16<1>, cudaFuncAttributeMaxDynamicSharedMemorySize, SMEM_H);
        cudaFuncSetAttribute(moe_mma16<2>, cudaFuncAttributeMaxDynamicSharedMemorySize, SMEM_H);
        configured = 1;
    }

    zero_cnt_kernel<<<1, 32>>>();
    ln_kernel<<<N_TOK, 256>>>(x, ln_g, ln_b);

    // weight prep (u64-interleaved fp16 packs)
    uint64_t *w1hp, *w1lp, *ew1p, *ew2p;
    cudaGetSymbolAddress((void**)&w1hp, g_w1hp);
    cudaGetSymbolAddress((void**)&w1lp, g_w1lp);
    cudaGetSymbolAddress((void**)&ew1p, g_ew1p);
    cudaGetSymbolAddress((void**)&ew2p, g_ew2p);
    packw2_split<<<(int)(((size_t)DIM * HHALF / 8) / 256), 256>>>(r_w1, w1hp, w1lp, HHALF);
    packw2<<<(int)(((size_t)NEXP * DIM * HID / 8) / 256), 256>>>(e_w1, ew1p, HID);
    packw2<<<(int)(((size_t)NEXP * HID * DIM / 8) / 256), 256>>>(e_w2, ew2p, DIM);

    // router path
    gemm_router16<<<dim3(HHALF / BN, N_TOK / BM), 256, SMEM_R>>>(w1hp, w1lp, r_b1);
    router_kernel<<<N_TOK / 8, 256>>>(r_w2, r_b2);
    scan_kernel<<<1, 32>>>();
    place_kernel<<<N_TOK / 256, 256>>>();

    // expert path
    moe_mma16<1><<<dim3(HID / BN, N_TOK / BM, NEXP), 256, SMEM_H>>>(ew1p, e_b1);
    moe_mma16<2><<<dim3(DIM / BN, N_TOK / BM, NEXP), 256, SMEM_H>>>(ew2p, e_b2);

    // out = x + g1*y1 + g2*y2
    combine_kernel<<<N_TOK, 256>>>(x, out);
}

// round 15
// speedup vs baseline: 2.1661x; 1.0057x over previous
#include <cuda_runtime.h>
#include <cuda_fp16.h>
#include <cstdint>

// Problem constants
#define N_TOK 16384
#define DIM   1024
#define HID   4096
#define HHALF 2048
#define NEXP  8
#define EPSLN 1e-5f

// CTA tile
#define BM 128
#define BN 256
#define B_ROWB 2080    // B smem row stride bytes (256 u64 + 32B pad): conflict-free LDS.64
#define B_ROWU 260     // same in u64

// ---------------- scratch -------------------------------------------------------
__device__ __half    g_xnh[(size_t)N_TOK * DIM];
__device__ __half    g_xnl[(size_t)N_TOK * DIM];
__device__ float     g_hr [(size_t)N_TOK * HHALF];
__device__ uint32_t  g_hh [(size_t)(2 * N_TOK) * (HID / 2)];
__device__ uint32_t  g_yh [(size_t)(2 * N_TOK) * (DIM / 2)];   // fp16 y, half2-packed
__device__ uint64_t  g_w1hp[(size_t)(DIM / 4) * HHALF];
__device__ uint64_t  g_w1lp[(size_t)(DIM / 4) * HHALF];
__device__ uint64_t  g_ew1p[(size_t)NEXP * (DIM / 4) * HID];
__device__ uint64_t  g_ew2p[(size_t)NEXP * (HID / 4) * DIM];
__device__ int   g_cnt[NEXP];
__device__ int   g_off[NEXP];
__device__ int   g_fill[NEXP];
__device__ int   g_e12[N_TOK];
__device__ float g_g1[N_TOK];
__device__ float g_g2[N_TOK];
__device__ int   g_list[2 * N_TOK];
__device__ int   g_s1[N_TOK];
__device__ int   g_s2[N_TOK];

// ---------------- helpers -------------------------------------------------------
__device__ __forceinline__ uint32_t smem_u32(const void* p) {
    uint32_t a;
    asm("{ .reg .u64 t; cvta.to.shared.u64 t, %1; cvt.u32.u64 %0, t; }" : "=r"(a) : "l"(p));
    return a;
}
#define CP16(dst, src) \
    asm volatile("cp.async.cg.shared.global [%0], [%1], 16;" :: "r"(dst), "l"(src) : "memory")
#define CP_COMMIT() asm volatile("cp.async.commit_group;" ::: "memory")
#define CP_WAIT2()  asm volatile("cp.async.wait_group 2;" ::: "memory")
#define CP_WAIT0()  asm volatile("cp.async.wait_group 0;" ::: "memory")

#define LDSM4(r0, r1, r2, r3, addr) \
    asm volatile("ldmatrix.sync.aligned.m8n8.x4.shared.b16 {%0,%1,%2,%3}, [%4];" \
                 : "=r"(r0), "=r"(r1), "=r"(r2), "=r"(r3) : "r"(addr))

__device__ __forceinline__ void mma16(float c[4], const uint32_t a[4], const uint32_t b[2]) {
    asm volatile(
        "mma.sync.aligned.m16n8k16.row.col.f32.f16.f16.f32 "
        "{%0,%1,%2,%3}, {%4,%5,%6,%7}, {%8,%9}, {%0,%1,%2,%3};"
        : "+f"(c[0]), "+f"(c[1]), "+f"(c[2]), "+f"(c[3])
        : "r"(a[0]), "r"(a[1]), "r"(a[2]), "r"(a[3]), "r"(b[0]), "r"(b[1]));
}

// ---------------- LayerNorm: fp16 hi + fp16 lo residual --------------------------
__global__ void ln_kernel(const float* __restrict__ x,
                          const float* __restrict__ gam,
                          const float* __restrict__ bet) {
    int row = blockIdx.x;
    const float* xr = x + (size_t)row * DIM;
    float s = 0.f, ss = 0.f;
    for (int i = threadIdx.x; i < DIM; i += 256) {
        float v = xr[i];
        s += v; ss += v * v;
    }
    __shared__ float sh[64];
    for (int o = 16; o; o >>= 1) {
        s  += __shfl_xor_sync(0xFFFFFFFFu, s,  o);
        ss += __shfl_xor_sync(0xFFFFFFFFu, ss, o);
    }
    int w = threadIdx.x >> 5, l = threadIdx.x & 31;
    if (l == 0) { sh[w] = s; sh[w + 32] = ss; }
    __syncthreads();
    if (w == 0) {
        s  = (l < 8) ? sh[l] : 0.f;
        ss = (l < 8) ? sh[l + 32] : 0.f;
        for (int o = 4; o; o >>= 1) {
            s  += __shfl_xor_sync(0xFFFFFFFFu, s,  o);
            ss += __shfl_xor_sync(0xFFFFFFFFu, ss, o);
        }
        if (l == 0) { sh[0] = s; sh[1] = ss; }
    }
    __syncthreads();
    float mu  = sh[0] * (1.0f / DIM);
    float var = sh[1] * (1.0f / DIM) - mu * mu;
    float r   = rsqrtf(var + EPSLN);
    for (int i = threadIdx.x; i < DIM; i += 256) {
        float v = (xr[i] - mu) * r * gam[i] + bet[i];
        __half h = __float2half_rn(v);
        g_xnh[(size_t)row * DIM + i] = h;
        g_xnl[(size_t)row * DIM + i] = __float2half_rn(v - __half2float(h));
    }
}

// ---------------- weight prep: u64-interleaved fp16 pack -------------------------
__global__ void packw2(const float* __restrict__ in, uint64_t* __restrict__ out,
                       int N) {
    size_t idx = (size_t)blockIdx.x * 256 + threadIdx.x;
    size_t nh = (size_t)N / 2;
    size_t rowp = idx / nh;
    size_t n = (idx % nh) * 2;
    size_t ko = rowp >> 2, lc = rowp & 3;
    size_t k0 = ko * 16 + lc * 2;
    const float* w0 = in + k0 * N + n;
    float a0 = w0[0],         a0b = w0[1];
    float a1 = w0[N],         a1b = w0[N + 1];
    float a8 = w0[8 * N],     a8b = w0[8 * N + 1];
    float a9 = w0[9 * N],     a9b = w0[9 * N + 1];
    __half2 h0 = __floats2half2_rn(a0, a1);
    __half2 h1 = __floats2half2_rn(a8, a9);
    __half2 h2 = __floats2half2_rn(a0b, a1b);
    __half2 h3 = __floats2half2_rn(a8b, a9b);
    uint4 o;
    o.x = *(uint32_t*)&h0; o.y = *(uint32_t*)&h1;
    o.z = *(uint32_t*)&h2; o.w = *(uint32_t*)&h3;
    *(uint4*)(out + rowp * N + n) = o;
}

__global__ void packw2_split(const float* __restrict__ in,
                             uint64_t* __restrict__ hi, uint64_t* __restrict__ lo,
                             int N) {
    size_t idx = (size_t)blockIdx.x * 256 + threadIdx.x;
    size_t nh = (size_t)N / 2;
    size_t rowp = idx / nh;
    size_t n = (idx % nh) * 2;
    size_t ko = rowp >> 2, lc = rowp & 3;
    size_t k0 = ko * 16 + lc * 2;
    const float* w0 = in + k0 * N + n;
    float v[8] = { w0[0], w0[N], w0[8 * N], w0[9 * N],
                   w0[1], w0[N + 1], w0[8 * N + 1], w0[9 * N + 1] };
    __half hh[8];
    __half ll[8];
#pragma unroll
    for (int j = 0; j < 8; j++) {
        hh[j] = __float2half_rn(v[j]);
        ll[j] = __float2half_rn(v[j] - __half2float(hh[j]));
    }
    uint4 oh, ol;
    __half2 t;
    t = __halves2half2(hh[0], hh[1]); oh.x = *(uint32_t*)&t;
    t = __halves2half2(hh[2], hh[3]); oh.y = *(uint32_t*)&t;
    t = __halves2half2(hh[4], hh[5]); oh.z = *(uint32_t*)&t;
    t = __halves2half2(hh[6], hh[7]); oh.w = *(uint32_t*)&t;
    t = __halves2half2(ll[0], ll[1]); ol.x = *(uint32_t*)&t;
    t = __halves2half2(ll[2], ll[3]); ol.y = *(uint32_t*)&t;
    t = __halves2half2(ll[4], ll[5]); ol.z = *(uint32_t*)&t;
    t = __halves2half2(ll[6], ll[7]); ol.w = *(uint32_t*)&t;
    *(uint4*)(hi + rowp * N + n) = oh;
    *(uint4*)(lo + rowp * N + n) = ol;
}

// ---------------- Router logits + softmax top-2 + gates --------------------------
__global__ void router_kernel(const float* __restrict__ w2,
                              const float* __restrict__ b2) {
    int warp = threadIdx.x >> 5, lane = threadIdx.x & 31;
    int t = blockIdx.x * 8 + warp;
    const float* hrow = g_hr + (size_t)t * HHALF;
    float acc[NEXP] = {};
    for (int i = lane; i < HHALF; i += 32) {
        float v = hrow[i];
        const float4* wp = (const float4*)(w2 + i * NEXP);
        float4 w0 = __ldg(wp), w1 = __ldg(wp + 1);
        acc[0] += v * w0.x; acc[1] += v * w0.y; acc[2] += v * w0.z; acc[3] += v * w0.w;
        acc[4] += v * w1.x; acc[5] += v * w1.y; acc[6] += v * w1.z; acc[7] += v * w1.w;
    }
    for (int o = 16; o; o >>= 1)
#pragma unroll
        for (int e = 0; e < NEXP; e++)
            acc[e] += __shfl_xor_sync(0xFFFFFFFFu, acc[e], o);
    if (lane == 0) {
        float l[NEXP];
#pragma unroll
        for (int e = 0; e < NEXP; e++) l[e] = acc[e] + b2[e];
        int e1 = 0;
        for (int e = 1; e < NEXP; e++) if (l[e] > l[e1]) e1 = e;
        int e2 = -1;
        for (int e = 0; e < NEXP; e++) {
            if (e == e1) continue;
            if (e2 < 0 || l[e] > l[e2]) e2 = e;
        }
        float ed  = expf(l[e2] - l[e1]);
        float inv = 1.f / (1.f + ed);
        g_e12[t] = e1 | (e2 << 8);
        g_g1[t] = inv;
        g_g2[t] = ed * inv;
        atomicAdd(&g_cnt[e1], 1);
        atomicAdd(&g_cnt[e2], 1);
    }
}

__global__ void zero_cnt_kernel() {
    if (threadIdx.x < NEXP) g_cnt[threadIdx.x] = 0;
}
__global__ void scan_kernel() {
    if (threadIdx.x == 0) {
        int s = 0;
        for (int e = 0; e < NEXP; e++) { g_off[e] = s; s += g_cnt[e]; g_fill[e] = 0; }
    }
}
__global__ void place_kernel() {
    int t = blockIdx.x * 256 + threadIdx.x;
    if (t >= N_TOK) return;
    int e12 = g_e12[t];
    int e1 = e12 & 0xFF, e2 = e12 >> 8;
    int s1 = g_off[e1] + atomicAdd(&g_fill[e1], 1);
    g_list[s1] = t; g_s1[t] = s1;
    int s2 = g_off[e2] + atomicAdd(&g_fill[e2], 1);
    g_list[s2] = t; g_s2[t] = s2;
}

// ---------------- final combine: out = x + g1*y[s1] + g2*y[s2] (y fp16) ----------
__global__ void combine_kernel(const float* __restrict__ x, float* __restrict__ out) {
    int t = blockIdx.x;
    int s1 = g_s1[t], s2 = g_s2[t];
    float a = g_g1[t], b = g_g2[t];
    int i = threadIdx.x;                       // 4 floats / 2 half2 per thread
    float4 xv = ((const float4*)(x + (size_t)t * DIM))[i];
    uint2 u1 = ((const uint2*)(g_yh + (size_t)s1 * (DIM / 2)))[i];
    uint2 u2 = ((const uint2*)(g_yh + (size_t)s2 * (DIM / 2)))[i];
    float2 p1a = __half22float2(*(__half2*)&u1.x);
    float2 p1b = __half22float2(*(__half2*)&u1.y);
    float2 p2a = __half22float2(*(__half2*)&u2.x);
    float2 p2b = __half22float2(*(__half2*)&u2.y);
    float4 r;
    r.x = xv.x + a * p1a.x + b * p2a.x;
    r.y = xv.y + a * p1a.y + b * p2a.y;
    r.z = xv.z + a * p1b.x + b * p2b.x;
    r.w = xv.w + a * p1b.y + b * p2b.y;
    ((float4*)(out + (size_t)t * DIM))[i] = r;
}

// ---------------- Router GEMM: split-fp16, ldmatrix + LDS.64, 4-stage ------------
__global__ void __launch_bounds__(256, 1)
gemm_router16(const uint64_t* __restrict__ Wh, const uint64_t* __restrict__ Wl,
              const float* __restrict__ bias) {
    constexpr int NC   = DIM / 32;
    constexpr int AST4 = 80;
    constexpr int ASZ  = BM * AST4;
    constexpr int BSZ  = 8 * B_ROWB;
    constexpr int STG  = 2 * ASZ + 2 * BSZ;   // 53760 B

    int bm = blockIdx.y * BM, bn = blockIdx.x * BN;
    extern __shared__ char smc[];
    uint32_t smb = smem_u32(smc);
    int tid = threadIdx.x, lane = tid & 31, wid = tid >> 5;
    int wm = (wid >> 2) * 64, wn = (wid & 3) * 64;

    const uint32_t* ah[2];
    const uint32_t* al[2];
    uint32_t adst[2];
#pragma unroll
    for (int j = 0; j < 2; j++) {
        int id = tid + 256 * j;
        int row = id >> 2, c4 = id & 3;
        adst[j] = (uint32_t)row * AST4 + c4 * 16;
        ah[j] = (const uint32_t*)g_xnh + (size_t)(bm + row) * (DIM / 2) + c4 * 4;
        al[j] = (const uint32_t*)g_xnl + (size_t)(bm + row) * (DIM / 2) + c4 * 4;
    }
    const uint64_t* bh[4];
    const uint64_t* bl[4];
    uint32_t bdst[4];
#pragma unroll
    for (int j = 0; j < 4; j++) {
        int id = tid + 256 * j;
        int p = id >> 7, nn = (id & 127) * 2;
        bdst[j] = (uint32_t)p * B_ROWB + nn * 8;
        bh[j] = Wh + (size_t)p * HHALF + bn + nn;
        bl[j] = Wl + (size_t)p * HHALF + bn + nn;
    }

    auto load = [&](int i, int st) {
        uint32_t s0 = smb + (uint32_t)st * STG;
        int ko = i * 16;
        size_t bko = (size_t)i * 8 * HHALF;
#pragma unroll
        for (int j = 0; j < 2; j++) {
            CP16(s0 + adst[j], ah[j] + ko);
            CP16(s0 + ASZ + adst[j], al[j] + ko);
        }
#pragma unroll
        for (int j = 0; j < 4; j++) {
            CP16(s0 + 2 * ASZ + bdst[j], bh[j] + bko);
            CP16(s0 + 2 * ASZ + BSZ + bdst[j], bl[j] + bko);
        }
        CP_COMMIT();
    };

    float c[4][8][4] = {};
    load(0, 0);
    load(1, 1);
    load(2, 2);

    int lr = lane >> 2, lc = lane & 3;
    uint32_t arow_off = (uint32_t)(wm + (lane & 15)) * AST4 + (lane >> 4) * 16;
    for (int i = 0; i < NC; i++) {
        int st = i & 3;
        if (i + 3 < NC) { CP_WAIT2(); } else { CP_WAIT0(); }
        __syncthreads();
        if (i + 3 < NC) load(i + 3, (i + 3) & 3);

        uint32_t sA  = smb + st * STG;
        uint32_t sA2 = sA + ASZ;
        const uint64_t* Bu = (const uint64_t*)(smc + st * STG + 2 * ASZ);
        const uint64_t* Bl2 = (const uint64_t*)(smc + st * STG + 2 * ASZ + BSZ);
#pragma unroll
        for (int ks = 0; ks < 2; ks++) {
            uint32_t a[4][4], a2[4][4], b[8][2], b2[8][2];
#pragma unroll
            for (int mt = 0; mt < 4; mt++) {
                LDSM4(a[mt][0], a[mt][1], a[mt][2], a[mt][3],
                      sA + arow_off + mt * 16 * AST4 + ks * 32);
                LDSM4(a2[mt][0], a2[mt][1], a2[mt][2], a2[mt][3],
                      sA2 + arow_off + mt * 16 * AST4 + ks * 32);
            }
            int prow = ks * 4 + lc;
#pragma unroll
            for (int nt = 0; nt < 8; nt++) {
                uint2 v  = *(const uint2*)(Bu  + (size_t)prow * B_ROWU + wn + nt * 8 + lr);
                uint2 v2 = *(const uint2*)(Bl2 + (size_t)prow * B_ROWU + wn + nt * 8 + lr);
                b[nt][0] = v.x;  b[nt][1] = v.y;
                b2[nt][0] = v2.x; b2[nt][1] = v2.y;
            }
#pragma unroll
            for (int mt = 0; mt < 4; mt++)
#pragma unroll
                for (int nt = 0; nt < 8; nt++) {
                    mma16(c[mt][nt], a[mt],  b[nt]);
                    mma16(c[mt][nt], a[mt],  b2[nt]);
                    mma16(c[mt][nt], a2[mt], b[nt]);
                }
        }
    }

#pragma unroll
    for (int mt = 0; mt < 4; mt++) {
#pragma unroll
        for (int half = 0; half < 2; half++) {
            int r = bm + wm + mt * 16 + lr + half * 8;
            float* row = g_hr + (size_t)r * HHALF;
#pragma unroll
            for (int nt = 0; nt < 8; nt++) {
                int col = bn + wn + nt * 8 + lc * 2;
                float v0 = c[mt][nt][half * 2]     + bias[col];
                float v1 = c[mt][nt][half * 2 + 1] + bias[col + 1];
                float2 st2;
                st2.x = fmaxf(v0, 0.f); st2.y = fmaxf(v1, 0.f);
                *(float2*)(row + col) = st2;
            }
        }
    }
}

// ---------------- Expert GEMMs: fp16, ldmatrix + LDS.64, BKC=64, 4-stage ---------
template <int MODE>
__global__ void __launch_bounds__(256, 1)
moe_mma16(const uint64_t* __restrict__ Wp, const float* __restrict__ bias) {
    constexpr int Kd   = (MODE == 2) ? HID : DIM;
    constexpr int Nd   = (MODE == 1) ? HID : DIM;
    constexpr int NC   = Kd / 64;
    constexpr int AST4 = 144;
    constexpr int ASZ  = BM * AST4;
    constexpr int BSZ  = 16 * B_ROWB;
    constexpr int STG  = ASZ + BSZ;          // 51712

    int bm = blockIdx.y * BM, bn = blockIdx.x * BN;
    int e = blockIdx.z;
    int cnt = g_cnt[e];
    if (bm >= cnt) return;
    int base = g_off[e];
    const uint64_t* W = Wp + (size_t)e * (Kd / 4) * Nd;
    const float* bp = bias + e * Nd;

    extern __shared__ char smc[];
    uint32_t smb = smem_u32(smc);
    int tid = threadIdx.x, lane = tid & 31, wid = tid >> 5;
    int wm = (wid >> 2) * 64, wn = (wid & 3) * 64;

    const uint32_t* ah[4];
    uint32_t adst[4];
#pragma unroll
    for (int j = 0; j < 4; j++) {
        int id = tid + 256 * j;
        int row = id >> 3, c4 = id & 7;
        adst[j] = (uint32_t)row * AST4 + c4 * 16;
        int r = bm + row; if (r >= cnt) r = cnt - 1;
        if (MODE == 1) {
            int tok = g_list[base + r];
            ah[j] = (const uint32_t*)g_xnh + (size_t)tok * (DIM / 2) + c4 * 4;
        } else {
            ah[j] = g_hh + (size_t)(base + r) * (HID / 2) + c4 * 4;
        }
    }
    const uint64_t* bh[8];
    uint32_t bdst[8];
#pragma unroll
    for (int j = 0; j < 8; j++) {
        int id = tid + 256 * j;
        int p = id >> 7, nn = (id & 127) * 2;
        bdst[j] = (uint32_t)p * B_ROWB + nn * 8;
        bh[j] = W + (size_t)p * Nd + bn + nn;
    }

    auto load = [&](int i, int st) {
        uint32_t s0 = smb + (uint32_t)st * STG;
        int ko = i * 32;                     // u32 offset along k (64 halves/chunk)
        size_t bko = (size_t)i * 16 * Nd;
#pragma unroll
        for (int j = 0; j < 4; j++) CP16(s0 + adst[j], ah[j] + ko);
#pragma unroll
        for (int j = 0; j < 8; j++) CP16(s0 + ASZ + bdst[j], bh[j] + bko);
        CP_COMMIT();
    };

    float c[4][8][4] = {};
    load(0, 0);
    load(1, 1);
    load(2, 2);

    int lr = lane >> 2, lc = lane & 3;
    uint32_t arow_off = (uint32_t)(wm + (lane & 15)) * AST4 + (lane >> 4) * 16;
    for (int i = 0; i < NC; i++) {
        int st = i & 3;
        if (i + 3 < NC) { CP_WAIT2(); } else { CP_WAIT0(); }
        __syncthreads();
        if (i + 3 < NC) load(i + 3, (i + 3) & 3);

        uint32_t sA = smb + st * STG;
        const uint64_t* Bu = (const uint64_t*)(smc + st * STG + ASZ);
#pragma unroll
        for (int ks = 0; ks < 4; ks++) {
            uint32_t a[4][4], b[8][2];
#pragma unroll
            for (int mt = 0; mt < 4; mt++)
                LDSM4(a[mt][0], a[mt][1], a[mt][2], a[mt][3],
                      sA + arow_off + mt * 16 * AST4 + ks * 32);
            int prow = ks * 4 + lc;
#pragma unroll
            for (int nt = 0; nt < 8; nt++) {
                uint2 v = *(const uint2*)(Bu + (size_t)prow * B_ROWU + wn + nt * 8 + lr);
                b[nt][0] = v.x; b[nt][1] = v.y;
            }
#pragma unroll
            for (int mt = 0; mt < 4; mt++)
#pragma unroll
                for (int nt = 0; nt < 8; nt++)
                    mma16(c[mt][nt], a[mt], b[nt]);
        }
    }

#pragma unroll
    for (int mt = 0; mt < 4; mt++) {
#pragma unroll
        for (int half = 0; half < 2; half++) {
            int r = bm + wm + mt * 16 + lr + half * 8;
            if (r >= cnt) continue;
            if (MODE == 1) {
                uint32_t* row = g_hh + (size_t)(base + r) * (HID / 2);
#pragma unroll
                for (int nt = 0; nt < 8; nt++) {
                    int col = bn + wn + nt * 8 + lc * 2;
                    float v0 = fmaxf(c[mt][nt][half * 2]     + bp[col],     0.f);
                    float v1 = fmaxf(c[mt][nt][half * 2 + 1] + bp[col + 1], 0.f);
                    __half2 hv = __floats2half2_rn(v0, v1);
                    row[col / 2] = *(uint32_t*)&hv;
                }
            } else {
                uint32_t* row = g_yh + (size_t)(base + r) * (DIM / 2);
#pragma unroll
                for (int nt = 0; nt < 8; nt++) {
                    int col = bn + wn + nt * 8 + lc * 2;
                    float v0 = c[mt][nt][half * 2]     + bp[col];
                    float v1 = c[mt][nt][half * 2 + 1] + bp[col + 1];
                    __half2 hv = __floats2half2_rn(v0, v1);
                    row[col / 2] = *(uint32_t*)&hv;
                }
            }
        }
    }
}

// ---------------- launch ---------------------------------------------------------
extern "C" void kernel_launch(void* const* d_in, const int* in_sizes, int n_in,
                              void* d_out, int out_size) {
    const float* x    = (const float*)d_in[0];
    const float* ln_g = (const float*)d_in[1];
    const float* ln_b = (const float*)d_in[2];
    const float* r_w1 = (const float*)d_in[3];
    const float* r_b1 = (const float*)d_in[4];
    const float* r_w2 = (const float*)d_in[5];
    const float* r_b2 = (const float*)d_in[6];
    const float* e_w1 = (const float*)d_in[7];
    const float* e_b1 = (const float*)d_in[8];
    const float* e_w2 = (const float*)d_in[9];
    const float* e_b2 = (const float*)d_in[10];
    float* out = (float*)d_out;

    const int SMEM_R = 4 * (2 * (BM * 80) + 2 * (8 * B_ROWB));    // 215040
    const int SMEM_H = 4 * (BM * 144 + 16 * B_ROWB);              // 206848

    static int configured = 0;
    if (!configured) {
        cudaFuncSetAttribute(gemm_router16, cudaFuncAttributeMaxDynamicSharedMemorySize, SMEM_R);
        cudaFuncSetAttribute(moe_mma16<1>, cudaFuncAttributeMaxDynamicSharedMemorySize, SMEM_H);
        cudaFuncSetAttribute(moe_mma16<2>, cudaFuncAttributeMaxDynamicSharedMemorySize, SMEM_H);
        configured = 1;
    }

    zero_cnt_kernel<<<1, 32>>>();
    ln_kernel<<<N_TOK, 256>>>(x, ln_g, ln_b);

    // weight prep (u64-interleaved fp16 packs)
    uint64_t *w1hp, *w1lp, *ew1p, *ew2p;
    cudaGetSymbolAddress((void**)&w1hp, g_w1hp);
    cudaGetSymbolAddress((void**)&w1lp, g_w1lp);
    cudaGetSymbolAddress((void**)&ew1p, g_ew1p);
    cudaGetSymbolAddress((void**)&ew2p, g_ew2p);
    packw2_split<<<(int)(((size_t)DIM * HHALF / 8) / 256), 256>>>(r_w1, w1hp, w1lp, HHALF);
    packw2<<<(int)(((size_t)NEXP * DIM * HID / 8) / 256), 256>>>(e_w1, ew1p, HID);
    packw2<<<(int)(((size_t)NEXP * HID * DIM / 8) / 256), 256>>>(e_w2, ew2p, DIM);

    // router path
    gemm_router16<<<dim3(HHALF / BN, N_TOK / BM), 256, SMEM_R>>>(w1hp, w1lp, r_b1);
    router_kernel<<<N_TOK / 8, 256>>>(r_w2, r_b2);
    scan_kernel<<<1, 32>>>();
    place_kernel<<<N_TOK / 256, 256>>>();

    // expert path
    moe_mma16<1><<<dim3(HID / BN, N_TOK / BM, NEXP), 256, SMEM_H>>>(ew1p, e_b1);
    moe_mma16<2><<<dim3(DIM / BN, N_TOK / BM, NEXP), 256, SMEM_H>>>(ew2p, e_b2);

    // out = x + g1*y1 + g2*y2
    combine_kernel<<<N_TOK, 256>>>(x, out);
}